// round 10
// baseline (speedup 1.0000x reference)
#include <cuda_runtime.h>
#include <cuda_fp16.h>
#include <math.h>
#include <stdint.h>
#include <limits.h>

#define NN 50000
#define NE 400000
#define NG 64

// ---------------- static scratch (no allocations allowed) ----------------
__device__ __align__(16) uint8_t d_M8[(size_t)NN * 384]; // messages, fp8 e4m3, plain order [h*C+c]
__device__ __align__(16) float d_aN[(size_t)NN * 4];     // leaky logits per node/head (fp32, from GEMM)
__device__ float d_h1[(size_t)NN * 96];
__device__ float d_h2[(size_t)NN * 96];
__device__ float d_h3[(size_t)NN * 64];
__device__ float d_S[(size_t)NN * 96];
__device__ int d_deg[NN];
__device__ int d_rowptr[NN + 1];
__device__ int d_cursor[NN];
__device__ int d_csrsrc[NE];
__device__ int d_gstart[NG + 1];
__device__ float d_pooled[NG * 64];
// W^T fp16: rows = GEMM output col (Wm | Ws | Watt), cols = K
__device__ __align__(16) __half d_Wh[(size_t)512 * 96];
__device__ __align__(16) float d_batt[4];   // att-contracted bias

// ---------------- fp8 helpers ----------------
__device__ __forceinline__ uint16_t f32x2_to_e4m3(float hi, float lo) {
    uint16_t o;
    asm("cvt.rn.satfinite.e4m3x2.f32 %0, %1, %2;" : "=h"(o) : "f"(hi), "f"(lo));
    return o;  // byte0 = lo, byte1 = hi
}
__device__ __forceinline__ __half2 e4m3x2_to_h2(uint16_t v) {
    uint32_t r;
    asm("cvt.rn.f16x2.e4m3x2 %0, %1;" : "=r"(r) : "h"(v));
    return *(__half2*)&r;  // .x = byte0, .y = byte1
}

// ---------------- CSR build ----------------
__global__ void k_degree(const int* __restrict__ dst) {
    int i = blockIdx.x * blockDim.x + threadIdx.x;
    if (i < NE) atomicAdd(&d_deg[dst[i]], 1);
}

// warp-shuffle exclusive scan of d_deg -> d_rowptr (+ cursor copy)
__global__ void k_scan() {
    __shared__ int wsum[32];
    __shared__ int carrySh;
    int tid = threadIdx.x;
    int lane = tid & 31, w = tid >> 5;
    if (tid == 0) carrySh = 0;
    __syncthreads();
    for (int base = 0; base < NN; base += 1024) {
        int i = base + tid;
        int v = (i < NN) ? d_deg[i] : 0;
        int incl = v;
        #pragma unroll
        for (int off = 1; off < 32; off <<= 1) {
            int t = __shfl_up_sync(0xffffffffu, incl, off);
            if (lane >= off) incl += t;
        }
        if (lane == 31) wsum[w] = incl;
        __syncthreads();
        if (w == 0) {
            int s = wsum[lane];
            #pragma unroll
            for (int off = 1; off < 32; off <<= 1) {
                int t = __shfl_up_sync(0xffffffffu, s, off);
                if (lane >= off) s += t;
            }
            wsum[lane] = s;
        }
        __syncthreads();
        int woff = (w > 0) ? wsum[w - 1] : 0;
        int carry = carrySh;
        int total = wsum[31];
        __syncthreads();
        if (i < NN) {
            int ex = carry + woff + incl - v;
            d_rowptr[i] = ex;
            d_cursor[i] = ex;
        }
        if (tid == 0) carrySh = carry + total;
        __syncthreads();
    }
    if (tid == 0) d_rowptr[NN] = carrySh;
}

__global__ void k_scatter(const int* __restrict__ src, const int* __restrict__ dst) {
    int i = blockIdx.x * blockDim.x + threadIdx.x;
    if (i < NE) {
        int p = atomicAdd(&d_cursor[dst[i]], 1);
        d_csrsrc[p] = src[i];
    }
}

// warp-per-node bitonic sort (ascending, deterministic); fallback insertion for d>32
__global__ void k_sortw() {
    int gw = (blockIdx.x * blockDim.x + threadIdx.x) >> 5;
    int lane = threadIdx.x & 31;
    if (gw >= NN) return;
    int s = d_rowptr[gw], e = d_rowptr[gw + 1];
    int d = e - s;
    if (d <= 1) return;
    if (d <= 32) {
        int v = (lane < d) ? d_csrsrc[s + lane] : INT_MAX;
        #pragma unroll
        for (int k = 2; k <= 32; k <<= 1) {
            #pragma unroll
            for (int j = k >> 1; j > 0; j >>= 1) {
                int other = __shfl_xor_sync(0xffffffffu, v, j);
                bool dirUp = ((lane & k) == 0);
                bool lower = ((lane & j) == 0);
                int mn = min(v, other), mx = max(v, other);
                v = (dirUp == lower) ? mn : mx;
            }
        }
        if (lane < d) d_csrsrc[s + lane] = v;
    } else if (lane == 0) {
        for (int i = s + 1; i < e; i++) {
            int v = d_csrsrc[i];
            int j = i - 1;
            while (j >= s && d_csrsrc[j] > v) {
                d_csrsrc[j + 1] = d_csrsrc[j];
                j--;
            }
            d_csrsrc[j + 1] = v;
        }
    }
}

// ---------------- weight conversions ----------------
__global__ void k_convW(const float* __restrict__ W, int K, int Nout, int rowOff) {
    int idx = blockIdx.x * blockDim.x + threadIdx.x;
    if (idx >= K * Nout) return;
    int k = idx / Nout, n = idx - k * Nout;
    d_Wh[(size_t)(rowOff + n) * K + k] = __float2half(W[idx]);
}

// Watt[k,h] = sum_c Wm[k, h*C+c]*att[h*C+c] -> rows rowA+h ; batt[h] = sum_c bm*att
__global__ void k_convAtt(const float* __restrict__ Wm, const float* __restrict__ att,
                          const float* __restrict__ bm, int K, int C, int rowA) {
    int t = threadIdx.x;
    int NC = 4 * C;
    if (t < K * 4) {
        int k = t >> 2, h = t & 3;
        float s = 0.f;
        for (int c = 0; c < C; c++) s += Wm[(size_t)k * NC + h * C + c] * att[h * C + c];
        d_Wh[(size_t)(rowA + h) * K + k] = __float2half(s);
    }
    if (t < 4) {
        float s = 0.f;
        for (int c = 0; c < C; c++) s += bm[t * C + c] * att[t * C + c];
        d_batt[t] = s;
    }
}

// ---------------- fp16 MMA GEMM (BK=32 loop, 16KB tiles) ----------------
// Column routing: [0,NsplitM) -> M8 fp8 (biasM); [NsplitM,NsplitA) -> S fp32 (biasS);
// [NsplitA,Nout) -> d_aN fp32 with leaky_relu (bias d_batt).
__device__ __forceinline__ uint32_t swz_off(int row, int c16) {
    return (uint32_t)((row << 6) + (((c16 ^ ((row >> 1) & 3)) & 3) << 4));
}

template <int K>
__global__ __launch_bounds__(256) void k_hgemm(
    const float* __restrict__ A,
    const float* __restrict__ biasM, const float* __restrict__ biasS,
    uint8_t* __restrict__ M8, float* __restrict__ S,
    int Mrows, int Nout, int NsplitM, int NsplitA, int strideM, int strideS)
{
    __shared__ __align__(16) char As[128 * 64];
    __shared__ __align__(16) char Bs[128 * 64];
    int tid = threadIdx.x;
    int wid = tid >> 5, lane = tid & 31;
    int r0 = blockIdx.x * 128;
    int n0 = blockIdx.y * 128;
    int wm = (wid & 3) * 32;
    int wn = (wid >> 2) * 64;

    uint32_t AsAddr = (uint32_t)__cvta_generic_to_shared(As);
    uint32_t BsAddr = (uint32_t)__cvta_generic_to_shared(Bs);

    float acc[2][8][4];
    #pragma unroll
    for (int i = 0; i < 2; i++)
        #pragma unroll
        for (int j = 0; j < 8; j++)
            #pragma unroll
            for (int q = 0; q < 4; q++) acc[i][j][q] = 0.f;

    #pragma unroll
    for (int kb = 0; kb < K; kb += 32) {
        #pragma unroll
        for (int it = 0; it < 2; it++) {
            int linear = tid + it * 256;
            int row = linear >> 2;
            int c8 = (linear & 3) << 3;
            int gr = r0 + row;
            float v[8];
            if (gr < Mrows) {
                float4 u0 = *(const float4*)(A + (size_t)gr * K + kb + c8);
                float4 u1 = *(const float4*)(A + (size_t)gr * K + kb + c8 + 4);
                v[0] = u0.x; v[1] = u0.y; v[2] = u0.z; v[3] = u0.w;
                v[4] = u1.x; v[5] = u1.y; v[6] = u1.z; v[7] = u1.w;
            } else {
                #pragma unroll
                for (int j = 0; j < 8; j++) v[j] = 0.f;
            }
            uint32_t pk[4];
            #pragma unroll
            for (int j = 0; j < 4; j++) {
                __half2 h = __floats2half2_rn(v[2 * j], v[2 * j + 1]);
                pk[j] = *(uint32_t*)&h;
            }
            *(uint4*)(As + swz_off(row, c8 >> 3)) = make_uint4(pk[0], pk[1], pk[2], pk[3]);
        }
        #pragma unroll
        for (int it = 0; it < 2; it++) {
            int linear = tid + it * 256;
            int row = linear >> 2;
            int c8 = (linear & 3) << 3;
            int gn = n0 + row;
            uint4 v = make_uint4(0u, 0u, 0u, 0u);
            if (gn < Nout)
                v = *(const uint4*)(d_Wh + (size_t)gn * K + kb + c8);
            *(uint4*)(Bs + swz_off(row, c8 >> 3)) = v;
        }
        __syncthreads();

        #pragma unroll
        for (int ks = 0; ks < 32; ks += 16) {
            uint32_t aF[2][4], bF[8][2];
            int q = lane >> 3;
            #pragma unroll
            for (int mt = 0; mt < 2; mt++) {
                int row = wm + mt * 16 + ((q & 1) << 3) + (lane & 7);
                int c16 = (ks >> 3) + (q >> 1);
                uint32_t addr = AsAddr + swz_off(row, c16);
                asm volatile("ldmatrix.sync.aligned.m8n8.x4.shared.b16 {%0,%1,%2,%3}, [%4];"
                    : "=r"(aF[mt][0]), "=r"(aF[mt][1]), "=r"(aF[mt][2]), "=r"(aF[mt][3])
                    : "r"(addr));
            }
            #pragma unroll
            for (int np = 0; np < 4; np++) {
                int row = wn + np * 16 + ((q >> 1) << 3) + (lane & 7);
                int c16 = (ks >> 3) + (q & 1);
                uint32_t addr = BsAddr + swz_off(row, c16);
                asm volatile("ldmatrix.sync.aligned.m8n8.x4.shared.b16 {%0,%1,%2,%3}, [%4];"
                    : "=r"(bF[2 * np][0]), "=r"(bF[2 * np][1]),
                      "=r"(bF[2 * np + 1][0]), "=r"(bF[2 * np + 1][1])
                    : "r"(addr));
            }
            #pragma unroll
            for (int mt = 0; mt < 2; mt++)
                #pragma unroll
                for (int nt = 0; nt < 8; nt++) {
                    asm volatile(
                        "mma.sync.aligned.m16n8k16.row.col.f32.f16.f16.f32 "
                        "{%0,%1,%2,%3}, {%4,%5,%6,%7}, {%8,%9}, {%0,%1,%2,%3};"
                        : "+f"(acc[mt][nt][0]), "+f"(acc[mt][nt][1]),
                          "+f"(acc[mt][nt][2]), "+f"(acc[mt][nt][3])
                        : "r"(aF[mt][0]), "r"(aF[mt][1]), "r"(aF[mt][2]), "r"(aF[mt][3]),
                          "r"(bF[nt][0]), "r"(bF[nt][1]));
                }
        }
        __syncthreads();
    }

    // ---- epilogue with 3-way column routing ----
    #pragma unroll
    for (int mt = 0; mt < 2; mt++) {
        int m = r0 + wm + mt * 16 + (lane >> 2);
        #pragma unroll
        for (int nt = 0; nt < 8; nt++) {
            int n = n0 + wn + nt * 8 + (lane & 3) * 2;
            if (n >= Nout) continue;
            if (n < NsplitM) {
                float2 bb = *(const float2*)(biasM + n);
                #pragma unroll
                for (int hf = 0; hf < 2; hf++) {
                    int mr = m + hf * 8;
                    if (mr < Mrows) {
                        uint16_t o = f32x2_to_e4m3(acc[mt][nt][2 * hf + 1] + bb.y,
                                                   acc[mt][nt][2 * hf] + bb.x);
                        *(uint16_t*)(M8 + (size_t)mr * strideM + n) = o;
                    }
                }
            } else if (n < NsplitA) {
                int nn = n - NsplitM;
                float2 bb = *(const float2*)(biasS + nn);
                #pragma unroll
                for (int hf = 0; hf < 2; hf++) {
                    int mr = m + hf * 8;
                    if (mr < Mrows) {
                        float2 o = make_float2(acc[mt][nt][2 * hf] + bb.x,
                                               acc[mt][nt][2 * hf + 1] + bb.y);
                        *(float2*)(S + (size_t)mr * strideS + nn) = o;
                    }
                }
            } else {
                int nn = n - NsplitA;
                float2 bb = *(const float2*)(d_batt + nn);
                #pragma unroll
                for (int hf = 0; hf < 2; hf++) {
                    int mr = m + hf * 8;
                    if (mr < Mrows) {
                        float vx = acc[mt][nt][2 * hf] + bb.x;
                        float vy = acc[mt][nt][2 * hf + 1] + bb.y;
                        vx = (vx > 0.f) ? vx : 0.2f * vx;
                        vy = (vy > 0.f) ? vy : 0.2f * vy;
                        *(float2*)(d_aN + (size_t)mr * 4 + nn) = make_float2(vx, vy);
                    }
                }
            }
        }
    }
}

// ---------------- aggregation: one warp per destination node ----------------
// fp8 payload; block-of-8 edges: ALL loads issued first (MLP 24), then FMA phase.
// Weight/index exchange via shuffles (no shared memory, no __syncwarp).
template <int C>
__global__ __launch_bounds__(256) void k_agg(
    const float* __restrict__ resid, float* __restrict__ out)
{
    const int HC = 4 * C;
    const int PL = HC / 32;      // fp8 bytes per lane (12 or 8)
    const int NW = PL / 4;       // u32 words per lane (3 or 2)
    int gw = (blockIdx.x * blockDim.x + threadIdx.x) >> 5;
    int lane = threadIdx.x & 31;
    if (gw >= NN) return;
    int start = d_rowptr[gw], end = d_rowptr[gw + 1];

    float m0 = -INFINITY, m1 = -INFINITY, m2 = -INFINITY, m3 = -INFINITY;
    for (int i = start + lane; i < end; i += 32) {
        int s = d_csrsrc[i];
        float4 a = *(const float4*)(d_aN + (size_t)s * 4);
        m0 = fmaxf(m0, a.x); m1 = fmaxf(m1, a.y);
        m2 = fmaxf(m2, a.z); m3 = fmaxf(m3, a.w);
    }
    #pragma unroll
    for (int off = 16; off > 0; off >>= 1) {
        m0 = fmaxf(m0, __shfl_xor_sync(0xffffffffu, m0, off));
        m1 = fmaxf(m1, __shfl_xor_sync(0xffffffffu, m1, off));
        m2 = fmaxf(m2, __shfl_xor_sync(0xffffffffu, m2, off));
        m3 = fmaxf(m3, __shfl_xor_sync(0xffffffffu, m3, off));
    }
    int h = lane >> 3;   // head owning this lane's channels
    int hh = lane & 3;
    int ei = lane >> 2;
    float mhh = (hh == 0) ? m0 : (hh == 1) ? m1 : (hh == 2) ? m2 : m3;

    __half2 acc2[NW * 2];
    #pragma unroll
    for (int j = 0; j < NW * 2; j++) acc2[j] = __float2half2_rn(0.f);
    float denL = 0.f;

    for (int base = start; base < end; base += 8) {
        int ne = end - base;
        if (ne > 8) ne = 8;
        // lane (4e+hh) computes weight of edge e, head hh
        float wl = 0.f;
        int sl = 0;
        if (ei < ne) {
            sl = d_csrsrc[base + ei];
            float a = d_aN[(size_t)sl * 4 + hh];
            wl = expf(a - mhh);
        }
        denL += wl;
        // ---- phase 1: issue ALL loads (MLP = ne*NW per lane) ----
        uint32_t wv[8][NW];
        #pragma unroll
        for (int e = 0; e < 8; e++) {
            if (e < ne) {
                int s = __shfl_sync(0xffffffffu, sl, e * 4);
                const uint32_t* rb = (const uint32_t*)(d_M8 + (size_t)s * HC + lane * PL);
                #pragma unroll
                for (int i = 0; i < NW; i++) wv[e][i] = rb[i];
            }
        }
        // ---- phase 2: convert + accumulate ----
        #pragma unroll
        for (int e = 0; e < 8; e++) {
            if (e < ne) {
                float wf = __shfl_sync(0xffffffffu, wl, e * 4 + h);
                __half2 wh = __float2half2_rn(wf);
                #pragma unroll
                for (int i = 0; i < NW; i++) {
                    acc2[2 * i] = __hfma2(e4m3x2_to_h2((uint16_t)wv[e][i]), wh, acc2[2 * i]);
                    acc2[2 * i + 1] = __hfma2(e4m3x2_to_h2((uint16_t)(wv[e][i] >> 16)), wh, acc2[2 * i + 1]);
                }
            }
        }
    }
    denL += __shfl_xor_sync(0xffffffffu, denL, 4);
    denL += __shfl_xor_sync(0xffffffffu, denL, 8);
    denL += __shfl_xor_sync(0xffffffffu, denL, 16);
    float den = __shfl_sync(0xffffffffu, denL, h);
    float inv = 0.25f / (den + 1e-16f);

    float acc[PL];
    #pragma unroll
    for (int j = 0; j < NW * 2; j++) {
        float2 t = __half22float2(acc2[j]);
        acc[2 * j] = t.x;
        acc[2 * j + 1] = t.y;
    }
    #pragma unroll
    for (int j = 0; j < PL; j++) {
        float v = acc[j] * inv;
        v += __shfl_xor_sync(0xffffffffu, v, 8);
        v += __shfl_xor_sync(0xffffffffu, v, 16);
        acc[j] = v;
    }
    if (lane < 8) {
        int col = lane * PL;
        #pragma unroll
        for (int q = 0; q < PL / 4; q++) {
            float4 r = *(const float4*)(resid + (size_t)gw * C + col + q * 4);
            float4 o;
            o.x = acc[q * 4 + 0] + r.x;
            o.y = acc[q * 4 + 1] + r.y;
            o.z = acc[q * 4 + 2] + r.z;
            o.w = acc[q * 4 + 3] + r.w;
            *(float4*)(out + (size_t)gw * C + col + q * 4) = o;
        }
    }
}

// ---------------- graph boundaries ----------------
__global__ void k_gstart(const int* __restrict__ batch) {
    int i = blockIdx.x * blockDim.x + threadIdx.x;
    if (i >= NN) return;
    int b = batch[i];
    int bp = (i == 0) ? -1 : batch[i - 1];
    for (int g = bp + 1; g <= b; g++) d_gstart[g] = i;
    if (i == NN - 1)
        for (int g = b + 1; g <= NG; g++) d_gstart[g] = NN;
}

// ---------------- global mean pool ----------------
__global__ void k_pool() {
    int g = blockIdx.x;
    int start = d_gstart[g], end = d_gstart[g + 1];
    int c = threadIdx.x & 63;
    int stripe = threadIdx.x >> 6;
    float acc = 0.f;
    for (int r = start + stripe; r < end; r += 4) acc += d_h3[(size_t)r * 64 + c];
    __shared__ float sh[256];
    sh[threadIdx.x] = acc;
    __syncthreads();
    if (stripe == 0) {
        float v = sh[c] + sh[c + 64] + sh[c + 128] + sh[c + 192];
        float cnt = (float)(end - start);
        d_pooled[g * 64 + c] = v / fmaxf(cnt, 1.0f);
    }
}

// ---------------- classifier + log_softmax ----------------
__global__ void k_fc(const float* __restrict__ Wfc, const float* __restrict__ bfc,
                     float* __restrict__ out) {
    int g = threadIdx.x;
    if (g >= NG) return;
    float logits[10];
    #pragma unroll
    for (int o = 0; o < 10; o++) {
        float s = bfc[o];
        for (int c = 0; c < 64; c++) s += d_pooled[g * 64 + c] * Wfc[c * 10 + o];
        logits[o] = s;
    }
    float mx = logits[0];
    #pragma unroll
    for (int o = 1; o < 10; o++) mx = fmaxf(mx, logits[o]);
    float se = 0.f;
    #pragma unroll
    for (int o = 0; o < 10; o++) se += expf(logits[o] - mx);
    float lse = mx + logf(se);
    #pragma unroll
    for (int o = 0; o < 10; o++) out[g * 10 + o] = logits[o] - lse;
}

// ---------------- launch ----------------
extern "C" void kernel_launch(void* const* d_in, const int* in_sizes, int n_in,
                              void* d_out, int out_size) {
    const float* x    = (const float*)d_in[0];
    const int* edge   = (const int*)d_in[1];
    const int* batch  = (const int*)d_in[2];
    const float* Wm1  = (const float*)d_in[3];
    const float* bm1  = (const float*)d_in[4];
    const float* att1 = (const float*)d_in[5];
    const float* Ws1  = (const float*)d_in[6];
    const float* bs1  = (const float*)d_in[7];
    const float* Wm2  = (const float*)d_in[8];
    const float* bm2  = (const float*)d_in[9];
    const float* att2 = (const float*)d_in[10];
    const float* Wm3  = (const float*)d_in[11];
    const float* bm3  = (const float*)d_in[12];
    const float* att3 = (const float*)d_in[13];
    const float* Ws3  = (const float*)d_in[14];
    const float* bs3  = (const float*)d_in[15];
    const float* Wfc  = (const float*)d_in[16];
    const float* bfc  = (const float*)d_in[17];
    float* out = (float*)d_out;

    const int* srcp = edge;
    const int* dstp = edge + NE;

    float *S, *h1, *h2, *h3;
    uint8_t* M8;
    int* degp;
    cudaGetSymbolAddress((void**)&S, d_S);
    cudaGetSymbolAddress((void**)&h1, d_h1);
    cudaGetSymbolAddress((void**)&h2, d_h2);
    cudaGetSymbolAddress((void**)&h3, d_h3);
    cudaGetSymbolAddress((void**)&M8, d_M8);
    cudaGetSymbolAddress((void**)&degp, d_deg);

    const int TB = 256;
    const int nodeBlocks = (NN + TB - 1) / TB;
    const int edgeBlocks = (NE + TB - 1) / TB;
    const int warpNodeBlocks = (NN * 32 + TB - 1) / TB;
    const int rowBlocks = (NN + 127) / 128;   // 391

    // CSR build
    cudaMemsetAsync(degp, 0, NN * sizeof(int));
    k_degree<<<edgeBlocks, TB>>>(dstp);
    k_scan<<<1, 1024>>>();
    k_scatter<<<edgeBlocks, TB>>>(srcp, dstp);
    k_sortw<<<warpNodeBlocks, TB>>>();

    // ---- layer 1: K=64, C=96; cols [0,384)M8 + [384,480)S + [480,484)aN ----
    k_convW<<<(64 * 384 + TB - 1) / TB, TB>>>(Wm1, 64, 384, 0);
    k_convW<<<(64 * 96 + TB - 1) / TB, TB>>>(Ws1, 64, 96, 384);
    k_convAtt<<<1, 512>>>(Wm1, att1, bm1, 64, 96, 480);
    k_hgemm<64><<<dim3(rowBlocks, 4), TB>>>(x, bm1, bs1, M8, S, NN, 484, 384, 480, 384, 96);
    k_agg<96><<<warpNodeBlocks, TB>>>(S, h1);

    // ---- layer 2: K=96, C=96; cols [0,384)M8 + [384,388)aN ----
    k_convW<<<(96 * 384 + TB - 1) / TB, TB>>>(Wm2, 96, 384, 0);
    k_convAtt<<<1, 512>>>(Wm2, att2, bm2, 96, 96, 384);
    k_hgemm<96><<<dim3(rowBlocks, 4), TB>>>(h1, bm2, bm2, M8, S, NN, 388, 384, 384, 384, 96);
    k_agg<96><<<warpNodeBlocks, TB>>>(h1, h2);

    // ---- layer 3: K=96, C=64; cols [0,256)M8 + [256,320)S + [320,324)aN ----
    k_convW<<<(96 * 256 + TB - 1) / TB, TB>>>(Wm3, 96, 256, 0);
    k_convW<<<(96 * 64 + TB - 1) / TB, TB>>>(Ws3, 96, 64, 256);
    k_convAtt<<<1, 512>>>(Wm3, att3, bm3, 96, 64, 320);
    k_hgemm<96><<<dim3(rowBlocks, 3), TB>>>(h2, bm3, bs3, M8, S, NN, 324, 256, 320, 256, 64);
    k_agg<64><<<warpNodeBlocks, TB>>>(S, h3);

    // ---- pool + classifier ----
    k_gstart<<<nodeBlocks, TB>>>(batch);
    k_pool<<<NG, 256>>>();
    k_fc<<<1, 64>>>(Wfc, bfc, out);
}

// round 12
// speedup vs baseline: 1.0383x; 1.0383x over previous
#include <cuda_runtime.h>
#include <cuda_fp16.h>
#include <math.h>
#include <stdint.h>
#include <limits.h>

#define NN 50000
#define NE 400000
#define NG 64

// ---------------- static scratch (no allocations allowed) ----------------
__device__ __align__(16) uint8_t d_M8[(size_t)NN * 384]; // messages, fp8 e4m3, plain order [h*C+c]
__device__ __align__(16) float d_aN[(size_t)NN * 4];     // leaky logits per node/head (fp32, from GEMM)
__device__ float d_h1[(size_t)NN * 96];
__device__ float d_h2[(size_t)NN * 96];
__device__ float d_h3[(size_t)NN * 64];
__device__ float d_S[(size_t)NN * 96];
__device__ int d_deg[NN];
__device__ int d_rowptr[NN + 1];
__device__ int d_cursor[NN];
__device__ int d_csrsrc[NE];
__device__ int d_gstart[NG + 1];
__device__ float d_pooled[NG * 64];
// W^T fp16: rows = GEMM output col (Wm | Ws | Watt), cols = K
__device__ __align__(16) __half d_Wh[(size_t)512 * 96];
__device__ __align__(16) float d_batt[4];   // att-contracted bias

// ---------------- fp8 helpers ----------------
__device__ __forceinline__ uint16_t f32x2_to_e4m3(float hi, float lo) {
    uint16_t o;
    asm("cvt.rn.satfinite.e4m3x2.f32 %0, %1, %2;" : "=h"(o) : "f"(hi), "f"(lo));
    return o;  // byte0 = lo, byte1 = hi
}
__device__ __forceinline__ __half2 e4m3x2_to_h2(uint16_t v) {
    uint32_t r;
    asm("cvt.rn.f16x2.e4m3x2 %0, %1;" : "=r"(r) : "h"(v));
    return *(__half2*)&r;  // .x = byte0, .y = byte1
}

// ---------------- CSR build ----------------
__global__ void k_degree(const int* __restrict__ dst) {
    int i = blockIdx.x * blockDim.x + threadIdx.x;
    if (i < NE) atomicAdd(&d_deg[dst[i]], 1);
}

// warp-shuffle exclusive scan of d_deg -> d_rowptr (+ cursor copy)
__global__ void k_scan() {
    __shared__ int wsum[32];
    __shared__ int carrySh;
    int tid = threadIdx.x;
    int lane = tid & 31, w = tid >> 5;
    if (tid == 0) carrySh = 0;
    __syncthreads();
    for (int base = 0; base < NN; base += 1024) {
        int i = base + tid;
        int v = (i < NN) ? d_deg[i] : 0;
        int incl = v;
        #pragma unroll
        for (int off = 1; off < 32; off <<= 1) {
            int t = __shfl_up_sync(0xffffffffu, incl, off);
            if (lane >= off) incl += t;
        }
        if (lane == 31) wsum[w] = incl;
        __syncthreads();
        if (w == 0) {
            int s = wsum[lane];
            #pragma unroll
            for (int off = 1; off < 32; off <<= 1) {
                int t = __shfl_up_sync(0xffffffffu, s, off);
                if (lane >= off) s += t;
            }
            wsum[lane] = s;
        }
        __syncthreads();
        int woff = (w > 0) ? wsum[w - 1] : 0;
        int carry = carrySh;
        int total = wsum[31];
        __syncthreads();
        if (i < NN) {
            int ex = carry + woff + incl - v;
            d_rowptr[i] = ex;
            d_cursor[i] = ex;
        }
        if (tid == 0) carrySh = carry + total;
        __syncthreads();
    }
    if (tid == 0) d_rowptr[NN] = carrySh;
}

__global__ void k_scatter(const int* __restrict__ src, const int* __restrict__ dst) {
    int i = blockIdx.x * blockDim.x + threadIdx.x;
    if (i < NE) {
        int p = atomicAdd(&d_cursor[dst[i]], 1);
        d_csrsrc[p] = src[i];
    }
}

// warp-per-node bitonic sort (ascending, deterministic); fallback insertion for d>32
__global__ void k_sortw() {
    int gw = (blockIdx.x * blockDim.x + threadIdx.x) >> 5;
    int lane = threadIdx.x & 31;
    if (gw >= NN) return;
    int s = d_rowptr[gw], e = d_rowptr[gw + 1];
    int d = e - s;
    if (d <= 1) return;
    if (d <= 32) {
        int v = (lane < d) ? d_csrsrc[s + lane] : INT_MAX;
        #pragma unroll
        for (int k = 2; k <= 32; k <<= 1) {
            #pragma unroll
            for (int j = k >> 1; j > 0; j >>= 1) {
                int other = __shfl_xor_sync(0xffffffffu, v, j);
                bool dirUp = ((lane & k) == 0);
                bool lower = ((lane & j) == 0);
                int mn = min(v, other), mx = max(v, other);
                v = (dirUp == lower) ? mn : mx;
            }
        }
        if (lane < d) d_csrsrc[s + lane] = v;
    } else if (lane == 0) {
        for (int i = s + 1; i < e; i++) {
            int v = d_csrsrc[i];
            int j = i - 1;
            while (j >= s && d_csrsrc[j] > v) {
                d_csrsrc[j + 1] = d_csrsrc[j];
                j--;
            }
            d_csrsrc[j + 1] = v;
        }
    }
}

// ---------------- weight conversions ----------------
__global__ void k_convW(const float* __restrict__ W, int K, int Nout, int rowOff) {
    int idx = blockIdx.x * blockDim.x + threadIdx.x;
    if (idx >= K * Nout) return;
    int k = idx / Nout, n = idx - k * Nout;
    d_Wh[(size_t)(rowOff + n) * K + k] = __float2half(W[idx]);
}

// Watt[k,h] = sum_c Wm[k, h*C+c]*att[h*C+c] -> rows rowA+h ; batt[h] = sum_c bm*att
__global__ void k_convAtt(const float* __restrict__ Wm, const float* __restrict__ att,
                          const float* __restrict__ bm, int K, int C, int rowA) {
    int t = threadIdx.x;
    int NC = 4 * C;
    if (t < K * 4) {
        int k = t >> 2, h = t & 3;
        float s = 0.f;
        for (int c = 0; c < C; c++) s += Wm[(size_t)k * NC + h * C + c] * att[h * C + c];
        d_Wh[(size_t)(rowA + h) * K + k] = __float2half(s);
    }
    if (t < 4) {
        float s = 0.f;
        for (int c = 0; c < C; c++) s += bm[t * C + c] * att[t * C + c];
        d_batt[t] = s;
    }
}

// ---------------- fp16 MMA GEMM (BK=32 loop, 16KB tiles) ----------------
// Column routing: [0,NsplitM) -> M8 fp8 (biasM); [NsplitM,NsplitA) -> S fp32 (biasS);
// [NsplitA,Nout) -> d_aN fp32 with leaky_relu (bias d_batt).
__device__ __forceinline__ uint32_t swz_off(int row, int c16) {
    return (uint32_t)((row << 6) + (((c16 ^ ((row >> 1) & 3)) & 3) << 4));
}

template <int K>
__global__ __launch_bounds__(256) void k_hgemm(
    const float* __restrict__ A,
    const float* __restrict__ biasM, const float* __restrict__ biasS,
    uint8_t* __restrict__ M8, float* __restrict__ S,
    int Mrows, int Nout, int NsplitM, int NsplitA, int strideM, int strideS)
{
    __shared__ __align__(16) char As[128 * 64];
    __shared__ __align__(16) char Bs[128 * 64];
    int tid = threadIdx.x;
    int wid = tid >> 5, lane = tid & 31;
    int r0 = blockIdx.x * 128;
    int n0 = blockIdx.y * 128;
    int wm = (wid & 3) * 32;
    int wn = (wid >> 2) * 64;

    uint32_t AsAddr = (uint32_t)__cvta_generic_to_shared(As);
    uint32_t BsAddr = (uint32_t)__cvta_generic_to_shared(Bs);

    float acc[2][8][4];
    #pragma unroll
    for (int i = 0; i < 2; i++)
        #pragma unroll
        for (int j = 0; j < 8; j++)
            #pragma unroll
            for (int q = 0; q < 4; q++) acc[i][j][q] = 0.f;

    #pragma unroll
    for (int kb = 0; kb < K; kb += 32) {
        #pragma unroll
        for (int it = 0; it < 2; it++) {
            int linear = tid + it * 256;
            int row = linear >> 2;
            int c8 = (linear & 3) << 3;
            int gr = r0 + row;
            float v[8];
            if (gr < Mrows) {
                float4 u0 = *(const float4*)(A + (size_t)gr * K + kb + c8);
                float4 u1 = *(const float4*)(A + (size_t)gr * K + kb + c8 + 4);
                v[0] = u0.x; v[1] = u0.y; v[2] = u0.z; v[3] = u0.w;
                v[4] = u1.x; v[5] = u1.y; v[6] = u1.z; v[7] = u1.w;
            } else {
                #pragma unroll
                for (int j = 0; j < 8; j++) v[j] = 0.f;
            }
            uint32_t pk[4];
            #pragma unroll
            for (int j = 0; j < 4; j++) {
                __half2 h = __floats2half2_rn(v[2 * j], v[2 * j + 1]);
                pk[j] = *(uint32_t*)&h;
            }
            *(uint4*)(As + swz_off(row, c8 >> 3)) = make_uint4(pk[0], pk[1], pk[2], pk[3]);
        }
        #pragma unroll
        for (int it = 0; it < 2; it++) {
            int linear = tid + it * 256;
            int row = linear >> 2;
            int c8 = (linear & 3) << 3;
            int gn = n0 + row;
            uint4 v = make_uint4(0u, 0u, 0u, 0u);
            if (gn < Nout)
                v = *(const uint4*)(d_Wh + (size_t)gn * K + kb + c8);
            *(uint4*)(Bs + swz_off(row, c8 >> 3)) = v;
        }
        __syncthreads();

        #pragma unroll
        for (int ks = 0; ks < 32; ks += 16) {
            uint32_t aF[2][4], bF[8][2];
            int q = lane >> 3;
            #pragma unroll
            for (int mt = 0; mt < 2; mt++) {
                int row = wm + mt * 16 + ((q & 1) << 3) + (lane & 7);
                int c16 = (ks >> 3) + (q >> 1);
                uint32_t addr = AsAddr + swz_off(row, c16);
                asm volatile("ldmatrix.sync.aligned.m8n8.x4.shared.b16 {%0,%1,%2,%3}, [%4];"
                    : "=r"(aF[mt][0]), "=r"(aF[mt][1]), "=r"(aF[mt][2]), "=r"(aF[mt][3])
                    : "r"(addr));
            }
            #pragma unroll
            for (int np = 0; np < 4; np++) {
                int row = wn + np * 16 + ((q >> 1) << 3) + (lane & 7);
                int c16 = (ks >> 3) + (q & 1);
                uint32_t addr = BsAddr + swz_off(row, c16);
                asm volatile("ldmatrix.sync.aligned.m8n8.x4.shared.b16 {%0,%1,%2,%3}, [%4];"
                    : "=r"(bF[2 * np][0]), "=r"(bF[2 * np][1]),
                      "=r"(bF[2 * np + 1][0]), "=r"(bF[2 * np + 1][1])
                    : "r"(addr));
            }
            #pragma unroll
            for (int mt = 0; mt < 2; mt++)
                #pragma unroll
                for (int nt = 0; nt < 8; nt++) {
                    asm volatile(
                        "mma.sync.aligned.m16n8k16.row.col.f32.f16.f16.f32 "
                        "{%0,%1,%2,%3}, {%4,%5,%6,%7}, {%8,%9}, {%0,%1,%2,%3};"
                        : "+f"(acc[mt][nt][0]), "+f"(acc[mt][nt][1]),
                          "+f"(acc[mt][nt][2]), "+f"(acc[mt][nt][3])
                        : "r"(aF[mt][0]), "r"(aF[mt][1]), "r"(aF[mt][2]), "r"(aF[mt][3]),
                          "r"(bF[nt][0]), "r"(bF[nt][1]));
                }
        }
        __syncthreads();
    }

    // ---- epilogue with 3-way column routing ----
    #pragma unroll
    for (int mt = 0; mt < 2; mt++) {
        int m = r0 + wm + mt * 16 + (lane >> 2);
        #pragma unroll
        for (int nt = 0; nt < 8; nt++) {
            int n = n0 + wn + nt * 8 + (lane & 3) * 2;
            if (n >= Nout) continue;
            if (n < NsplitM) {
                float2 bb = *(const float2*)(biasM + n);
                #pragma unroll
                for (int hf = 0; hf < 2; hf++) {
                    int mr = m + hf * 8;
                    if (mr < Mrows) {
                        uint16_t o = f32x2_to_e4m3(acc[mt][nt][2 * hf + 1] + bb.y,
                                                   acc[mt][nt][2 * hf] + bb.x);
                        *(uint16_t*)(M8 + (size_t)mr * strideM + n) = o;
                    }
                }
            } else if (n < NsplitA) {
                int nn = n - NsplitM;
                float2 bb = *(const float2*)(biasS + nn);
                #pragma unroll
                for (int hf = 0; hf < 2; hf++) {
                    int mr = m + hf * 8;
                    if (mr < Mrows) {
                        float2 o = make_float2(acc[mt][nt][2 * hf] + bb.x,
                                               acc[mt][nt][2 * hf + 1] + bb.y);
                        *(float2*)(S + (size_t)mr * strideS + nn) = o;
                    }
                }
            } else {
                int nn = n - NsplitA;
                float2 bb = *(const float2*)(d_batt + nn);
                #pragma unroll
                for (int hf = 0; hf < 2; hf++) {
                    int mr = m + hf * 8;
                    if (mr < Mrows) {
                        float vx = acc[mt][nt][2 * hf] + bb.x;
                        float vy = acc[mt][nt][2 * hf + 1] + bb.y;
                        vx = (vx > 0.f) ? vx : 0.2f * vx;
                        vy = (vy > 0.f) ? vy : 0.2f * vy;
                        *(float2*)(d_aN + (size_t)mr * 4 + nn) = make_float2(vx, vy);
                    }
                }
            }
        }
    }
}

// ---------------- aggregation: one warp per destination node ----------------
// R9 structure (smem exchange, fp8 payload) + depth-2 prefetch pipeline in the e-loop.
template <int C>
__global__ __launch_bounds__(256) void k_agg(
    const float* __restrict__ resid, float* __restrict__ out)
{
    const int HC = 4 * C;
    const int PL = HC / 32;      // fp8 bytes per lane (12 or 8)
    const int NW = PL / 4;       // u32 words per lane (3 or 2)
    __shared__ float wsh[8][8][4];
    __shared__ int ssh[8][8];
    int gw = (blockIdx.x * blockDim.x + threadIdx.x) >> 5;
    int lane = threadIdx.x & 31;
    int wId = threadIdx.x >> 5;
    if (gw >= NN) return;
    int start = d_rowptr[gw], end = d_rowptr[gw + 1];

    float m0 = -INFINITY, m1 = -INFINITY, m2 = -INFINITY, m3 = -INFINITY;
    for (int i = start + lane; i < end; i += 32) {
        int s = d_csrsrc[i];
        float4 a = *(const float4*)(d_aN + (size_t)s * 4);
        m0 = fmaxf(m0, a.x); m1 = fmaxf(m1, a.y);
        m2 = fmaxf(m2, a.z); m3 = fmaxf(m3, a.w);
    }
    #pragma unroll
    for (int off = 16; off > 0; off >>= 1) {
        m0 = fmaxf(m0, __shfl_xor_sync(0xffffffffu, m0, off));
        m1 = fmaxf(m1, __shfl_xor_sync(0xffffffffu, m1, off));
        m2 = fmaxf(m2, __shfl_xor_sync(0xffffffffu, m2, off));
        m3 = fmaxf(m3, __shfl_xor_sync(0xffffffffu, m3, off));
    }
    int h = lane >> 3;   // head owning this lane's channels
    int hh = lane & 3;
    float mhh = (hh == 0) ? m0 : (hh == 1) ? m1 : (hh == 2) ? m2 : m3;

    __half2 acc2[NW * 2];
    #pragma unroll
    for (int j = 0; j < NW * 2; j++) acc2[j] = __float2half2_rn(0.f);
    float denL = 0.f;
    int ei = lane >> 2;

    for (int base = start; base < end; base += 8) {
        int ne = end - base;
        if (ne > 8) ne = 8;
        if (ei < ne) {
            int sl = d_csrsrc[base + ei];
            float a = d_aN[(size_t)sl * 4 + hh];
            float wl = expf(a - mhh);
            denL += wl;
            wsh[wId][ei][hh] = wl;
            if (hh == 0) ssh[wId][ei] = sl;
        }
        __syncwarp();
        // depth-2 pipeline: prefetch edge e+1 while accumulating edge e
        uint32_t cur[NW], nxt[NW];
        {
            const uint32_t* rb = (const uint32_t*)(d_M8 + (size_t)ssh[wId][0] * HC + lane * PL);
            #pragma unroll
            for (int i = 0; i < NW; i++) cur[i] = rb[i];
        }
        #pragma unroll
        for (int e = 0; e < 8; e++) {
            if (e >= ne) break;
            if (e + 1 < ne) {
                const uint32_t* rb = (const uint32_t*)(d_M8 + (size_t)ssh[wId][e + 1] * HC + lane * PL);
                #pragma unroll
                for (int i = 0; i < NW; i++) nxt[i] = rb[i];
            }
            __half2 wh = __float2half2_rn(wsh[wId][e][h]);
            #pragma unroll
            for (int i = 0; i < NW; i++) {
                acc2[2 * i] = __hfma2(e4m3x2_to_h2((uint16_t)cur[i]), wh, acc2[2 * i]);
                acc2[2 * i + 1] = __hfma2(e4m3x2_to_h2((uint16_t)(cur[i] >> 16)), wh, acc2[2 * i + 1]);
            }
            #pragma unroll
            for (int i = 0; i < NW; i++) cur[i] = nxt[i];
        }
        __syncwarp();
    }
    denL += __shfl_xor_sync(0xffffffffu, denL, 4);
    denL += __shfl_xor_sync(0xffffffffu, denL, 8);
    denL += __shfl_xor_sync(0xffffffffu, denL, 16);
    float den = __shfl_sync(0xffffffffu, denL, h);
    float inv = 0.25f / (den + 1e-16f);

    float acc[PL];
    #pragma unroll
    for (int j = 0; j < NW * 2; j++) {
        float2 t = __half22float2(acc2[j]);
        acc[2 * j] = t.x;
        acc[2 * j + 1] = t.y;
    }
    #pragma unroll
    for (int j = 0; j < PL; j++) {
        float v = acc[j] * inv;
        v += __shfl_xor_sync(0xffffffffu, v, 8);
        v += __shfl_xor_sync(0xffffffffu, v, 16);
        acc[j] = v;
    }
    if (lane < 8) {
        int col = lane * PL;
        #pragma unroll
        for (int q = 0; q < PL / 4; q++) {
            float4 r = *(const float4*)(resid + (size_t)gw * C + col + q * 4);
            float4 o;
            o.x = acc[q * 4 + 0] + r.x;
            o.y = acc[q * 4 + 1] + r.y;
            o.z = acc[q * 4 + 2] + r.z;
            o.w = acc[q * 4 + 3] + r.w;
            *(float4*)(out + (size_t)gw * C + col + q * 4) = o;
        }
    }
}

// ---------------- graph boundaries ----------------
__global__ void k_gstart(const int* __restrict__ batch) {
    int i = blockIdx.x * blockDim.x + threadIdx.x;
    if (i >= NN) return;
    int b = batch[i];
    int bp = (i == 0) ? -1 : batch[i - 1];
    for (int g = bp + 1; g <= b; g++) d_gstart[g] = i;
    if (i == NN - 1)
        for (int g = b + 1; g <= NG; g++) d_gstart[g] = NN;
}

// ---------------- global mean pool ----------------
__global__ void k_pool() {
    int g = blockIdx.x;
    int start = d_gstart[g], end = d_gstart[g + 1];
    int c = threadIdx.x & 63;
    int stripe = threadIdx.x >> 6;
    float acc = 0.f;
    for (int r = start + stripe; r < end; r += 4) acc += d_h3[(size_t)r * 64 + c];
    __shared__ float sh[256];
    sh[threadIdx.x] = acc;
    __syncthreads();
    if (stripe == 0) {
        float v = sh[c] + sh[c + 64] + sh[c + 128] + sh[c + 192];
        float cnt = (float)(end - start);
        d_pooled[g * 64 + c] = v / fmaxf(cnt, 1.0f);
    }
}

// ---------------- classifier + log_softmax ----------------
__global__ void k_fc(const float* __restrict__ Wfc, const float* __restrict__ bfc,
                     float* __restrict__ out) {
    int g = threadIdx.x;
    if (g >= NG) return;
    float logits[10];
    #pragma unroll
    for (int o = 0; o < 10; o++) {
        float s = bfc[o];
        for (int c = 0; c < 64; c++) s += d_pooled[g * 64 + c] * Wfc[c * 10 + o];
        logits[o] = s;
    }
    float mx = logits[0];
    #pragma unroll
    for (int o = 1; o < 10; o++) mx = fmaxf(mx, logits[o]);
    float se = 0.f;
    #pragma unroll
    for (int o = 0; o < 10; o++) se += expf(logits[o] - mx);
    float lse = mx + logf(se);
    #pragma unroll
    for (int o = 0; o < 10; o++) out[g * 10 + o] = logits[o] - lse;
}

// ---------------- launch ----------------
extern "C" void kernel_launch(void* const* d_in, const int* in_sizes, int n_in,
                              void* d_out, int out_size) {
    const float* x    = (const float*)d_in[0];
    const int* edge   = (const int*)d_in[1];
    const int* batch  = (const int*)d_in[2];
    const float* Wm1  = (const float*)d_in[3];
    const float* bm1  = (const float*)d_in[4];
    const float* att1 = (const float*)d_in[5];
    const float* Ws1  = (const float*)d_in[6];
    const float* bs1  = (const float*)d_in[7];
    const float* Wm2  = (const float*)d_in[8];
    const float* bm2  = (const float*)d_in[9];
    const float* att2 = (const float*)d_in[10];
    const float* Wm3  = (const float*)d_in[11];
    const float* bm3  = (const float*)d_in[12];
    const float* att3 = (const float*)d_in[13];
    const float* Ws3  = (const float*)d_in[14];
    const float* bs3  = (const float*)d_in[15];
    const float* Wfc  = (const float*)d_in[16];
    const float* bfc  = (const float*)d_in[17];
    float* out = (float*)d_out;

    const int* srcp = edge;
    const int* dstp = edge + NE;

    float *S, *h1, *h2, *h3;
    uint8_t* M8;
    int* degp;
    cudaGetSymbolAddress((void**)&S, d_S);
    cudaGetSymbolAddress((void**)&h1, d_h1);
    cudaGetSymbolAddress((void**)&h2, d_h2);
    cudaGetSymbolAddress((void**)&h3, d_h3);
    cudaGetSymbolAddress((void**)&M8, d_M8);
    cudaGetSymbolAddress((void**)&degp, d_deg);

    const int TB = 256;
    const int nodeBlocks = (NN + TB - 1) / TB;
    const int edgeBlocks = (NE + TB - 1) / TB;
    const int warpNodeBlocks = (NN * 32 + TB - 1) / TB;
    const int rowBlocks = (NN + 127) / 128;   // 391

    // CSR build
    cudaMemsetAsync(degp, 0, NN * sizeof(int));
    k_degree<<<edgeBlocks, TB>>>(dstp);
    k_scan<<<1, 1024>>>();
    k_scatter<<<edgeBlocks, TB>>>(srcp, dstp);
    k_sortw<<<warpNodeBlocks, TB>>>();

    // ---- layer 1: K=64, C=96; cols [0,384)M8 + [384,480)S + [480,484)aN ----
    k_convW<<<(64 * 384 + TB - 1) / TB, TB>>>(Wm1, 64, 384, 0);
    k_convW<<<(64 * 96 + TB - 1) / TB, TB>>>(Ws1, 64, 96, 384);
    k_convAtt<<<1, 512>>>(Wm1, att1, bm1, 64, 96, 480);
    k_hgemm<64><<<dim3(rowBlocks, 4), TB>>>(x, bm1, bs1, M8, S, NN, 484, 384, 480, 384, 96);
    k_agg<96><<<warpNodeBlocks, TB>>>(S, h1);

    // ---- layer 2: K=96, C=96; cols [0,384)M8 + [384,388)aN ----
    k_convW<<<(96 * 384 + TB - 1) / TB, TB>>>(Wm2, 96, 384, 0);
    k_convAtt<<<1, 512>>>(Wm2, att2, bm2, 96, 96, 384);
    k_hgemm<96><<<dim3(rowBlocks, 4), TB>>>(h1, bm2, bm2, M8, S, NN, 388, 384, 384, 384, 96);
    k_agg<96><<<warpNodeBlocks, TB>>>(h1, h2);

    // ---- layer 3: K=96, C=64; cols [0,256)M8 + [256,320)S + [320,324)aN ----
    k_convW<<<(96 * 256 + TB - 1) / TB, TB>>>(Wm3, 96, 256, 0);
    k_convW<<<(96 * 64 + TB - 1) / TB, TB>>>(Ws3, 96, 64, 256);
    k_convAtt<<<1, 512>>>(Wm3, att3, bm3, 96, 64, 320);
    k_hgemm<96><<<dim3(rowBlocks, 3), TB>>>(h2, bm3, bs3, M8, S, NN, 324, 256, 320, 256, 64);
    k_agg<64><<<warpNodeBlocks, TB>>>(S, h3);

    // ---- pool + classifier ----
    k_gstart<<<nodeBlocks, TB>>>(batch);
    k_pool<<<NG, 256>>>();
    k_fc<<<1, 64>>>(Wfc, bfc, out);
}

// round 13
// speedup vs baseline: 1.3164x; 1.2678x over previous
#include <cuda_runtime.h>
#include <cuda_fp16.h>
#include <math.h>
#include <stdint.h>
#include <limits.h>

#define NN 50000
#define NE 400000
#define NG 64

// ---------------- static scratch (no allocations allowed) ----------------
__device__ __align__(16) uint8_t d_M8[(size_t)NN * 384]; // messages, fp8 e4m3, plain order [h*C+c]
__device__ __align__(16) float d_aN[(size_t)NN * 4];     // leaky logits per node/head (fp32, from GEMM)
__device__ float d_h1[(size_t)NN * 96];
__device__ float d_h2[(size_t)NN * 96];
__device__ float d_h3[(size_t)NN * 64];
__device__ float d_S[(size_t)NN * 96];
__device__ int d_deg[NN];
__device__ int d_rowptr[NN + 1];
__device__ int d_cursor[NN];
__device__ int d_csrsrc[NE];
__device__ int d_gstart[NG + 1];
__device__ float d_pooled[NG * 64];
// W^T fp16: rows = GEMM output col (Wm | Ws | Watt), cols = K
__device__ __align__(16) __half d_Wh[(size_t)512 * 96];
__device__ __align__(16) float d_batt[4];   // att-contracted bias

// ---------------- fp8 helpers ----------------
__device__ __forceinline__ uint16_t f32x2_to_e4m3(float hi, float lo) {
    uint16_t o;
    asm("cvt.rn.satfinite.e4m3x2.f32 %0, %1, %2;" : "=h"(o) : "f"(hi), "f"(lo));
    return o;  // byte0 = lo, byte1 = hi
}
__device__ __forceinline__ __half2 e4m3x2_to_h2(uint16_t v) {
    uint32_t r;
    asm("cvt.rn.f16x2.e4m3x2 %0, %1;" : "=r"(r) : "h"(v));
    return *(__half2*)&r;  // .x = byte0, .y = byte1
}

// ---------------- CSR build ----------------
__global__ void k_degree(const int* __restrict__ dst) {
    int i = blockIdx.x * blockDim.x + threadIdx.x;
    if (i < NE) atomicAdd(&d_deg[dst[i]], 1);
}

// warp-shuffle exclusive scan of d_deg -> d_rowptr (+ cursor copy)
__global__ void k_scan() {
    __shared__ int wsum[32];
    __shared__ int carrySh;
    int tid = threadIdx.x;
    int lane = tid & 31, w = tid >> 5;
    if (tid == 0) carrySh = 0;
    __syncthreads();
    for (int base = 0; base < NN; base += 1024) {
        int i = base + tid;
        int v = (i < NN) ? d_deg[i] : 0;
        int incl = v;
        #pragma unroll
        for (int off = 1; off < 32; off <<= 1) {
            int t = __shfl_up_sync(0xffffffffu, incl, off);
            if (lane >= off) incl += t;
        }
        if (lane == 31) wsum[w] = incl;
        __syncthreads();
        if (w == 0) {
            int s = wsum[lane];
            #pragma unroll
            for (int off = 1; off < 32; off <<= 1) {
                int t = __shfl_up_sync(0xffffffffu, s, off);
                if (lane >= off) s += t;
            }
            wsum[lane] = s;
        }
        __syncthreads();
        int woff = (w > 0) ? wsum[w - 1] : 0;
        int carry = carrySh;
        int total = wsum[31];
        __syncthreads();
        if (i < NN) {
            int ex = carry + woff + incl - v;
            d_rowptr[i] = ex;
            d_cursor[i] = ex;
        }
        if (tid == 0) carrySh = carry + total;
        __syncthreads();
    }
    if (tid == 0) d_rowptr[NN] = carrySh;
}

__global__ void k_scatter(const int* __restrict__ src, const int* __restrict__ dst) {
    int i = blockIdx.x * blockDim.x + threadIdx.x;
    if (i < NE) {
        int p = atomicAdd(&d_cursor[dst[i]], 1);
        d_csrsrc[p] = src[i];
    }
}

// warp-per-node bitonic sort (ascending, deterministic); fallback insertion for d>32
__global__ void k_sortw() {
    int gw = (blockIdx.x * blockDim.x + threadIdx.x) >> 5;
    int lane = threadIdx.x & 31;
    if (gw >= NN) return;
    int s = d_rowptr[gw], e = d_rowptr[gw + 1];
    int d = e - s;
    if (d <= 1) return;
    if (d <= 32) {
        int v = (lane < d) ? d_csrsrc[s + lane] : INT_MAX;
        #pragma unroll
        for (int k = 2; k <= 32; k <<= 1) {
            #pragma unroll
            for (int j = k >> 1; j > 0; j >>= 1) {
                int other = __shfl_xor_sync(0xffffffffu, v, j);
                bool dirUp = ((lane & k) == 0);
                bool lower = ((lane & j) == 0);
                int mn = min(v, other), mx = max(v, other);
                v = (dirUp == lower) ? mn : mx;
            }
        }
        if (lane < d) d_csrsrc[s + lane] = v;
    } else if (lane == 0) {
        for (int i = s + 1; i < e; i++) {
            int v = d_csrsrc[i];
            int j = i - 1;
            while (j >= s && d_csrsrc[j] > v) {
                d_csrsrc[j + 1] = d_csrsrc[j];
                j--;
            }
            d_csrsrc[j + 1] = v;
        }
    }
}

// ---------------- weight conversions ----------------
__global__ void k_convW(const float* __restrict__ W, int K, int Nout, int rowOff) {
    int idx = blockIdx.x * blockDim.x + threadIdx.x;
    if (idx >= K * Nout) return;
    int k = idx / Nout, n = idx - k * Nout;
    d_Wh[(size_t)(rowOff + n) * K + k] = __float2half(W[idx]);
}

// Watt[k,h] = sum_c Wm[k, h*C+c]*att[h*C+c] -> rows rowA+h ; batt[h] = sum_c bm*att
__global__ void k_convAtt(const float* __restrict__ Wm, const float* __restrict__ att,
                          const float* __restrict__ bm, int K, int C, int rowA) {
    int t = threadIdx.x;
    int NC = 4 * C;
    if (t < K * 4) {
        int k = t >> 2, h = t & 3;
        float s = 0.f;
        for (int c = 0; c < C; c++) s += Wm[(size_t)k * NC + h * C + c] * att[h * C + c];
        d_Wh[(size_t)(rowA + h) * K + k] = __float2half(s);
    }
    if (t < 4) {
        float s = 0.f;
        for (int c = 0; c < C; c++) s += bm[t * C + c] * att[t * C + c];
        d_batt[t] = s;
    }
}

// ---------------- fp16 MMA GEMM (BK=32 loop, 16KB tiles) ----------------
// Column routing: [0,NsplitM) -> M8 fp8 (biasM); [NsplitM,NsplitA) -> S fp32 (biasS);
// [NsplitA,Nout) -> d_aN fp32 with leaky_relu (bias d_batt).
__device__ __forceinline__ uint32_t swz_off(int row, int c16) {
    return (uint32_t)((row << 6) + (((c16 ^ ((row >> 1) & 3)) & 3) << 4));
}

template <int K>
__global__ __launch_bounds__(256) void k_hgemm(
    const float* __restrict__ A,
    const float* __restrict__ biasM, const float* __restrict__ biasS,
    uint8_t* __restrict__ M8, float* __restrict__ S,
    int Mrows, int Nout, int NsplitM, int NsplitA, int strideM, int strideS)
{
    __shared__ __align__(16) char As[128 * 64];
    __shared__ __align__(16) char Bs[128 * 64];
    int tid = threadIdx.x;
    int wid = tid >> 5, lane = tid & 31;
    int r0 = blockIdx.x * 128;
    int n0 = blockIdx.y * 128;
    int wm = (wid & 3) * 32;
    int wn = (wid >> 2) * 64;

    uint32_t AsAddr = (uint32_t)__cvta_generic_to_shared(As);
    uint32_t BsAddr = (uint32_t)__cvta_generic_to_shared(Bs);

    float acc[2][8][4];
    #pragma unroll
    for (int i = 0; i < 2; i++)
        #pragma unroll
        for (int j = 0; j < 8; j++)
            #pragma unroll
            for (int q = 0; q < 4; q++) acc[i][j][q] = 0.f;

    #pragma unroll
    for (int kb = 0; kb < K; kb += 32) {
        #pragma unroll
        for (int it = 0; it < 2; it++) {
            int linear = tid + it * 256;
            int row = linear >> 2;
            int c8 = (linear & 3) << 3;
            int gr = r0 + row;
            float v[8];
            if (gr < Mrows) {
                float4 u0 = *(const float4*)(A + (size_t)gr * K + kb + c8);
                float4 u1 = *(const float4*)(A + (size_t)gr * K + kb + c8 + 4);
                v[0] = u0.x; v[1] = u0.y; v[2] = u0.z; v[3] = u0.w;
                v[4] = u1.x; v[5] = u1.y; v[6] = u1.z; v[7] = u1.w;
            } else {
                #pragma unroll
                for (int j = 0; j < 8; j++) v[j] = 0.f;
            }
            uint32_t pk[4];
            #pragma unroll
            for (int j = 0; j < 4; j++) {
                __half2 h = __floats2half2_rn(v[2 * j], v[2 * j + 1]);
                pk[j] = *(uint32_t*)&h;
            }
            *(uint4*)(As + swz_off(row, c8 >> 3)) = make_uint4(pk[0], pk[1], pk[2], pk[3]);
        }
        #pragma unroll
        for (int it = 0; it < 2; it++) {
            int linear = tid + it * 256;
            int row = linear >> 2;
            int c8 = (linear & 3) << 3;
            int gn = n0 + row;
            uint4 v = make_uint4(0u, 0u, 0u, 0u);
            if (gn < Nout)
                v = *(const uint4*)(d_Wh + (size_t)gn * K + kb + c8);
            *(uint4*)(Bs + swz_off(row, c8 >> 3)) = v;
        }
        __syncthreads();

        #pragma unroll
        for (int ks = 0; ks < 32; ks += 16) {
            uint32_t aF[2][4], bF[8][2];
            int q = lane >> 3;
            #pragma unroll
            for (int mt = 0; mt < 2; mt++) {
                int row = wm + mt * 16 + ((q & 1) << 3) + (lane & 7);
                int c16 = (ks >> 3) + (q >> 1);
                uint32_t addr = AsAddr + swz_off(row, c16);
                asm volatile("ldmatrix.sync.aligned.m8n8.x4.shared.b16 {%0,%1,%2,%3}, [%4];"
                    : "=r"(aF[mt][0]), "=r"(aF[mt][1]), "=r"(aF[mt][2]), "=r"(aF[mt][3])
                    : "r"(addr));
            }
            #pragma unroll
            for (int np = 0; np < 4; np++) {
                int row = wn + np * 16 + ((q >> 1) << 3) + (lane & 7);
                int c16 = (ks >> 3) + (q & 1);
                uint32_t addr = BsAddr + swz_off(row, c16);
                asm volatile("ldmatrix.sync.aligned.m8n8.x4.shared.b16 {%0,%1,%2,%3}, [%4];"
                    : "=r"(bF[2 * np][0]), "=r"(bF[2 * np][1]),
                      "=r"(bF[2 * np + 1][0]), "=r"(bF[2 * np + 1][1])
                    : "r"(addr));
            }
            #pragma unroll
            for (int mt = 0; mt < 2; mt++)
                #pragma unroll
                for (int nt = 0; nt < 8; nt++) {
                    asm volatile(
                        "mma.sync.aligned.m16n8k16.row.col.f32.f16.f16.f32 "
                        "{%0,%1,%2,%3}, {%4,%5,%6,%7}, {%8,%9}, {%0,%1,%2,%3};"
                        : "+f"(acc[mt][nt][0]), "+f"(acc[mt][nt][1]),
                          "+f"(acc[mt][nt][2]), "+f"(acc[mt][nt][3])
                        : "r"(aF[mt][0]), "r"(aF[mt][1]), "r"(aF[mt][2]), "r"(aF[mt][3]),
                          "r"(bF[nt][0]), "r"(bF[nt][1]));
                }
        }
        __syncthreads();
    }

    // ---- epilogue with 3-way column routing ----
    #pragma unroll
    for (int mt = 0; mt < 2; mt++) {
        int m = r0 + wm + mt * 16 + (lane >> 2);
        #pragma unroll
        for (int nt = 0; nt < 8; nt++) {
            int n = n0 + wn + nt * 8 + (lane & 3) * 2;
            if (n >= Nout) continue;
            if (n < NsplitM) {
                float2 bb = *(const float2*)(biasM + n);
                #pragma unroll
                for (int hf = 0; hf < 2; hf++) {
                    int mr = m + hf * 8;
                    if (mr < Mrows) {
                        uint16_t o = f32x2_to_e4m3(acc[mt][nt][2 * hf + 1] + bb.y,
                                                   acc[mt][nt][2 * hf] + bb.x);
                        *(uint16_t*)(M8 + (size_t)mr * strideM + n) = o;
                    }
                }
            } else if (n < NsplitA) {
                int nn = n - NsplitM;
                float2 bb = *(const float2*)(biasS + nn);
                #pragma unroll
                for (int hf = 0; hf < 2; hf++) {
                    int mr = m + hf * 8;
                    if (mr < Mrows) {
                        float2 o = make_float2(acc[mt][nt][2 * hf] + bb.x,
                                               acc[mt][nt][2 * hf + 1] + bb.y);
                        *(float2*)(S + (size_t)mr * strideS + nn) = o;
                    }
                }
            } else {
                int nn = n - NsplitA;
                float2 bb = *(const float2*)(d_batt + nn);
                #pragma unroll
                for (int hf = 0; hf < 2; hf++) {
                    int mr = m + hf * 8;
                    if (mr < Mrows) {
                        float vx = acc[mt][nt][2 * hf] + bb.x;
                        float vy = acc[mt][nt][2 * hf + 1] + bb.y;
                        vx = (vx > 0.f) ? vx : 0.2f * vx;
                        vy = (vy > 0.f) ? vy : 0.2f * vy;
                        *(float2*)(d_aN + (size_t)mr * 4 + nn) = make_float2(vx, vy);
                    }
                }
            }
        }
    }
}

// ---------------- aggregation: one warp per destination node (R9 exact) ----------------
template <int C>
__global__ __launch_bounds__(256) void k_agg(
    const float* __restrict__ resid, float* __restrict__ out)
{
    const int HC = 4 * C;
    const int PL = HC / 32;      // fp8 bytes per lane (12 or 8)
    const int NW = PL / 4;       // u32 words per lane (3 or 2)
    __shared__ float wsh[8][8][4];
    __shared__ int ssh[8][8];
    int gw = (blockIdx.x * blockDim.x + threadIdx.x) >> 5;
    int lane = threadIdx.x & 31;
    int wId = threadIdx.x >> 5;
    if (gw >= NN) return;
    int start = d_rowptr[gw], end = d_rowptr[gw + 1];

    float m0 = -INFINITY, m1 = -INFINITY, m2 = -INFINITY, m3 = -INFINITY;
    for (int i = start + lane; i < end; i += 32) {
        int s = d_csrsrc[i];
        float4 a = *(const float4*)(d_aN + (size_t)s * 4);
        m0 = fmaxf(m0, a.x); m1 = fmaxf(m1, a.y);
        m2 = fmaxf(m2, a.z); m3 = fmaxf(m3, a.w);
    }
    #pragma unroll
    for (int off = 16; off > 0; off >>= 1) {
        m0 = fmaxf(m0, __shfl_xor_sync(0xffffffffu, m0, off));
        m1 = fmaxf(m1, __shfl_xor_sync(0xffffffffu, m1, off));
        m2 = fmaxf(m2, __shfl_xor_sync(0xffffffffu, m2, off));
        m3 = fmaxf(m3, __shfl_xor_sync(0xffffffffu, m3, off));
    }
    int h = lane >> 3;   // head owning this lane's channels
    int hh = lane & 3;
    float mhh = (hh == 0) ? m0 : (hh == 1) ? m1 : (hh == 2) ? m2 : m3;

    __half2 acc2[NW * 2];
    #pragma unroll
    for (int j = 0; j < NW * 2; j++) acc2[j] = __float2half2_rn(0.f);
    float denL = 0.f;
    int ei = lane >> 2;

    for (int base = start; base < end; base += 8) {
        int ne = end - base;
        if (ne > 8) ne = 8;
        if (ei < ne) {
            int sl = d_csrsrc[base + ei];
            float a = d_aN[(size_t)sl * 4 + hh];
            float wl = expf(a - mhh);
            denL += wl;
            wsh[wId][ei][hh] = wl;
            if (hh == 0) ssh[wId][ei] = sl;
        }
        __syncwarp();
        for (int e = 0; e < ne; e++) {
            int s = ssh[wId][e];
            __half2 wh = __float2half2_rn(wsh[wId][e][h]);
            const uint32_t* rb = (const uint32_t*)(d_M8 + (size_t)s * HC + lane * PL);
            uint32_t wv[NW];
            #pragma unroll
            for (int i = 0; i < NW; i++) wv[i] = rb[i];
            #pragma unroll
            for (int i = 0; i < NW; i++) {
                acc2[2 * i] = __hfma2(e4m3x2_to_h2((uint16_t)wv[i]), wh, acc2[2 * i]);
                acc2[2 * i + 1] = __hfma2(e4m3x2_to_h2((uint16_t)(wv[i] >> 16)), wh, acc2[2 * i + 1]);
            }
        }
        __syncwarp();
    }
    denL += __shfl_xor_sync(0xffffffffu, denL, 4);
    denL += __shfl_xor_sync(0xffffffffu, denL, 8);
    denL += __shfl_xor_sync(0xffffffffu, denL, 16);
    float den = __shfl_sync(0xffffffffu, denL, h);
    float inv = 0.25f / (den + 1e-16f);

    float acc[PL];
    #pragma unroll
    for (int j = 0; j < NW * 2; j++) {
        float2 t = __half22float2(acc2[j]);
        acc[2 * j] = t.x;
        acc[2 * j + 1] = t.y;
    }
    #pragma unroll
    for (int j = 0; j < PL; j++) {
        float v = acc[j] * inv;
        v += __shfl_xor_sync(0xffffffffu, v, 8);
        v += __shfl_xor_sync(0xffffffffu, v, 16);
        acc[j] = v;
    }
    if (lane < 8) {
        int col = lane * PL;
        #pragma unroll
        for (int q = 0; q < PL / 4; q++) {
            float4 r = *(const float4*)(resid + (size_t)gw * C + col + q * 4);
            float4 o;
            o.x = acc[q * 4 + 0] + r.x;
            o.y = acc[q * 4 + 1] + r.y;
            o.z = acc[q * 4 + 2] + r.z;
            o.w = acc[q * 4 + 3] + r.w;
            *(float4*)(out + (size_t)gw * C + col + q * 4) = o;
        }
    }
}

// ---------------- graph boundaries ----------------
__global__ void k_gstart(const int* __restrict__ batch) {
    int i = blockIdx.x * blockDim.x + threadIdx.x;
    if (i >= NN) return;
    int b = batch[i];
    int bp = (i == 0) ? -1 : batch[i - 1];
    for (int g = bp + 1; g <= b; g++) d_gstart[g] = i;
    if (i == NN - 1)
        for (int g = b + 1; g <= NG; g++) d_gstart[g] = NN;
}

// ---------------- global mean pool ----------------
__global__ void k_pool() {
    int g = blockIdx.x;
    int start = d_gstart[g], end = d_gstart[g + 1];
    int c = threadIdx.x & 63;
    int stripe = threadIdx.x >> 6;
    float acc = 0.f;
    for (int r = start + stripe; r < end; r += 4) acc += d_h3[(size_t)r * 64 + c];
    __shared__ float sh[256];
    sh[threadIdx.x] = acc;
    __syncthreads();
    if (stripe == 0) {
        float v = sh[c] + sh[c + 64] + sh[c + 128] + sh[c + 192];
        float cnt = (float)(end - start);
        d_pooled[g * 64 + c] = v / fmaxf(cnt, 1.0f);
    }
}

// ---------------- classifier + log_softmax ----------------
__global__ void k_fc(const float* __restrict__ Wfc, const float* __restrict__ bfc,
                     float* __restrict__ out) {
    int g = threadIdx.x;
    if (g >= NG) return;
    float logits[10];
    #pragma unroll
    for (int o = 0; o < 10; o++) {
        float s = bfc[o];
        for (int c = 0; c < 64; c++) s += d_pooled[g * 64 + c] * Wfc[c * 10 + o];
        logits[o] = s;
    }
    float mx = logits[0];
    #pragma unroll
    for (int o = 1; o < 10; o++) mx = fmaxf(mx, logits[o]);
    float se = 0.f;
    #pragma unroll
    for (int o = 0; o < 10; o++) se += expf(logits[o] - mx);
    float lse = mx + logf(se);
    #pragma unroll
    for (int o = 0; o < 10; o++) out[g * 10 + o] = logits[o] - lse;
}

// ---------------- launch (dual-stream overlap: CSR || GEMM chain) ----------------
extern "C" void kernel_launch(void* const* d_in, const int* in_sizes, int n_in,
                              void* d_out, int out_size) {
    const float* x    = (const float*)d_in[0];
    const int* edge   = (const int*)d_in[1];
    const int* batch  = (const int*)d_in[2];
    const float* Wm1  = (const float*)d_in[3];
    const float* bm1  = (const float*)d_in[4];
    const float* att1 = (const float*)d_in[5];
    const float* Ws1  = (const float*)d_in[6];
    const float* bs1  = (const float*)d_in[7];
    const float* Wm2  = (const float*)d_in[8];
    const float* bm2  = (const float*)d_in[9];
    const float* att2 = (const float*)d_in[10];
    const float* Wm3  = (const float*)d_in[11];
    const float* bm3  = (const float*)d_in[12];
    const float* att3 = (const float*)d_in[13];
    const float* Ws3  = (const float*)d_in[14];
    const float* bs3  = (const float*)d_in[15];
    const float* Wfc  = (const float*)d_in[16];
    const float* bfc  = (const float*)d_in[17];
    float* out = (float*)d_out;

    const int* srcp = edge;
    const int* dstp = edge + NE;

    float *S, *h1, *h2, *h3;
    uint8_t* M8;
    int* degp;
    cudaGetSymbolAddress((void**)&S, d_S);
    cudaGetSymbolAddress((void**)&h1, d_h1);
    cudaGetSymbolAddress((void**)&h2, d_h2);
    cudaGetSymbolAddress((void**)&h3, d_h3);
    cudaGetSymbolAddress((void**)&M8, d_M8);
    cudaGetSymbolAddress((void**)&degp, d_deg);

    static cudaStream_t s2 = nullptr;
    static cudaEvent_t evFork, evG1, evC2, evH2, evC3;
    if (!s2) {
        cudaStreamCreateWithFlags(&s2, cudaStreamNonBlocking);
        cudaEventCreateWithFlags(&evFork, cudaEventDisableTiming);
        cudaEventCreateWithFlags(&evG1, cudaEventDisableTiming);
        cudaEventCreateWithFlags(&evC2, cudaEventDisableTiming);
        cudaEventCreateWithFlags(&evH2, cudaEventDisableTiming);
        cudaEventCreateWithFlags(&evC3, cudaEventDisableTiming);
    }

    const int TB = 256;
    const int nodeBlocks = (NN + TB - 1) / TB;
    const int edgeBlocks = (NE + TB - 1) / TB;
    const int warpNodeBlocks = (NN * 32 + TB - 1) / TB;
    const int rowBlocks = (NN + 127) / 128;   // 391
    cudaStream_t s0 = 0;   // capturing stream

    // ---- fork: branch B (weights + layer-1 GEMM) on s2 ----
    cudaEventRecord(evFork, s0);
    cudaStreamWaitEvent(s2, evFork, 0);

    // branch A (s0): CSR build
    cudaMemsetAsync(degp, 0, NN * sizeof(int), s0);
    k_degree<<<edgeBlocks, TB, 0, s0>>>(dstp);
    k_scan<<<1, 1024, 0, s0>>>();
    k_scatter<<<edgeBlocks, TB, 0, s0>>>(srcp, dstp);
    k_sortw<<<warpNodeBlocks, TB, 0, s0>>>();

    // branch B (s2): layer-1 weights + GEMM
    k_convW<<<(64 * 384 + TB - 1) / TB, TB, 0, s2>>>(Wm1, 64, 384, 0);
    k_convW<<<(64 * 96 + TB - 1) / TB, TB, 0, s2>>>(Ws1, 64, 96, 384);
    k_convAtt<<<1, 512, 0, s2>>>(Wm1, att1, bm1, 64, 96, 480);
    k_hgemm<64><<<dim3(rowBlocks, 4), TB, 0, s2>>>(x, bm1, bs1, M8, S, NN, 484, 384, 480, 384, 96);
    cudaEventRecord(evG1, s2);

    // layer-2 weight conversions on s2 (d_Wh no longer read by hgemm1; overlaps agg1)
    k_convW<<<(96 * 384 + TB - 1) / TB, TB, 0, s2>>>(Wm2, 96, 384, 0);
    k_convAtt<<<1, 512, 0, s2>>>(Wm2, att2, bm2, 96, 96, 384);
    cudaEventRecord(evC2, s2);

    // ---- join for agg1: needs CSR (s0 order) + GEMM1 (evG1) ----
    cudaStreamWaitEvent(s0, evG1, 0);
    k_agg<96><<<warpNodeBlocks, TB, 0, s0>>>(S, h1);

    // ---- layer 2 GEMM: needs h1 (s0) + conv2 (evC2) ----
    cudaStreamWaitEvent(s0, evC2, 0);
    k_hgemm<96><<<dim3(rowBlocks, 4), TB, 0, s0>>>(h1, bm2, bm2, M8, S, NN, 388, 384, 384, 384, 96);
    cudaEventRecord(evH2, s0);

    // layer-3 weight conversions on s2 after hgemm2 released d_Wh; overlaps agg2
    cudaStreamWaitEvent(s2, evH2, 0);
    k_convW<<<(96 * 256 + TB - 1) / TB, TB, 0, s2>>>(Wm3, 96, 256, 0);
    k_convW<<<(96 * 64 + TB - 1) / TB, TB, 0, s2>>>(Ws3, 96, 64, 256);
    k_convAtt<<<1, 512, 0, s2>>>(Wm3, att3, bm3, 96, 64, 320);
    cudaEventRecord(evC3, s2);

    k_agg<96><<<warpNodeBlocks, TB, 0, s0>>>(h1, h2);

    // ---- layer 3 GEMM: needs h2 (s0) + conv3 (evC3) ----
    cudaStreamWaitEvent(s0, evC3, 0);
    k_hgemm<96><<<dim3(rowBlocks, 3), TB, 0, s0>>>(h2, bm3, bs3, M8, S, NN, 324, 256, 320, 256, 64);
    k_agg<64><<<warpNodeBlocks, TB, 0, s0>>>(S, h3);

    // ---- pool + classifier ----
    k_gstart<<<nodeBlocks, TB, 0, s0>>>(batch);
    k_pool<<<NG, 256, 0, s0>>>();
    k_fc<<<1, 64, 0, s0>>>(Wfc, bfc, out);
}

// round 14
// speedup vs baseline: 1.3243x; 1.0060x over previous
#include <cuda_runtime.h>
#include <cuda_fp16.h>
#include <math.h>
#include <stdint.h>
#include <limits.h>

#define NN 50000
#define NE 400000
#define NG 64
#define NS 25088   // half split: 196 row-blocks of 128

// ---------------- static scratch (no allocations allowed) ----------------
__device__ __align__(16) uint8_t d_M8A[(size_t)NN * 384];
__device__ __align__(16) uint8_t d_M8B[(size_t)NN * 384];
__device__ __align__(16) float d_aNA[(size_t)NN * 4];
__device__ __align__(16) float d_aNB[(size_t)NN * 4];
__device__ float d_h1[(size_t)NN * 96];
__device__ float d_h2[(size_t)NN * 96];
__device__ float d_h3[(size_t)NN * 64];
__device__ float d_S[(size_t)NN * 96];
__device__ int d_deg[NN];
__device__ int d_rowptr[NN + 1];
__device__ int d_cursor[NN];
__device__ int d_csrsrc[NE];
__device__ int d_gstart[NG + 1];
__device__ float d_pooled[NG * 64];
__device__ __align__(16) __half d_Wh[(size_t)512 * 96];
__device__ __align__(16) float d_batt[4];

// ---------------- fp8 helpers ----------------
__device__ __forceinline__ uint16_t f32x2_to_e4m3(float hi, float lo) {
    uint16_t o;
    asm("cvt.rn.satfinite.e4m3x2.f32 %0, %1, %2;" : "=h"(o) : "f"(hi), "f"(lo));
    return o;
}
__device__ __forceinline__ __half2 e4m3x2_to_h2(uint16_t v) {
    uint32_t r;
    asm("cvt.rn.f16x2.e4m3x2 %0, %1;" : "=r"(r) : "h"(v));
    return *(__half2*)&r;
}

// ---------------- CSR build ----------------
__global__ void k_degree(const int* __restrict__ dst) {
    int i = blockIdx.x * blockDim.x + threadIdx.x;
    if (i < NE) atomicAdd(&d_deg[dst[i]], 1);
}

__global__ void k_scan() {
    __shared__ int wsum[32];
    __shared__ int carrySh;
    int tid = threadIdx.x;
    int lane = tid & 31, w = tid >> 5;
    if (tid == 0) carrySh = 0;
    __syncthreads();
    for (int base = 0; base < NN; base += 1024) {
        int i = base + tid;
        int v = (i < NN) ? d_deg[i] : 0;
        int incl = v;
        #pragma unroll
        for (int off = 1; off < 32; off <<= 1) {
            int t = __shfl_up_sync(0xffffffffu, incl, off);
            if (lane >= off) incl += t;
        }
        if (lane == 31) wsum[w] = incl;
        __syncthreads();
        if (w == 0) {
            int s = wsum[lane];
            #pragma unroll
            for (int off = 1; off < 32; off <<= 1) {
                int t = __shfl_up_sync(0xffffffffu, s, off);
                if (lane >= off) s += t;
            }
            wsum[lane] = s;
        }
        __syncthreads();
        int woff = (w > 0) ? wsum[w - 1] : 0;
        int carry = carrySh;
        int total = wsum[31];
        __syncthreads();
        if (i < NN) {
            int ex = carry + woff + incl - v;
            d_rowptr[i] = ex;
            d_cursor[i] = ex;
        }
        if (tid == 0) carrySh = carry + total;
        __syncthreads();
    }
    if (tid == 0) d_rowptr[NN] = carrySh;
}

__global__ void k_scatter(const int* __restrict__ src, const int* __restrict__ dst) {
    int i = blockIdx.x * blockDim.x + threadIdx.x;
    if (i < NE) {
        int p = atomicAdd(&d_cursor[dst[i]], 1);
        d_csrsrc[p] = src[i];
    }
}

__global__ void k_sortw() {
    int gw = (blockIdx.x * blockDim.x + threadIdx.x) >> 5;
    int lane = threadIdx.x & 31;
    if (gw >= NN) return;
    int s = d_rowptr[gw], e = d_rowptr[gw + 1];
    int d = e - s;
    if (d <= 1) return;
    if (d <= 32) {
        int v = (lane < d) ? d_csrsrc[s + lane] : INT_MAX;
        #pragma unroll
        for (int k = 2; k <= 32; k <<= 1) {
            #pragma unroll
            for (int j = k >> 1; j > 0; j >>= 1) {
                int other = __shfl_xor_sync(0xffffffffu, v, j);
                bool dirUp = ((lane & k) == 0);
                bool lower = ((lane & j) == 0);
                int mn = min(v, other), mx = max(v, other);
                v = (dirUp == lower) ? mn : mx;
            }
        }
        if (lane < d) d_csrsrc[s + lane] = v;
    } else if (lane == 0) {
        for (int i = s + 1; i < e; i++) {
            int v = d_csrsrc[i];
            int j = i - 1;
            while (j >= s && d_csrsrc[j] > v) {
                d_csrsrc[j + 1] = d_csrsrc[j];
                j--;
            }
            d_csrsrc[j + 1] = v;
        }
    }
}

// ---------------- weight conversions ----------------
__global__ void k_convW(const float* __restrict__ W, int K, int Nout, int rowOff) {
    int idx = blockIdx.x * blockDim.x + threadIdx.x;
    if (idx >= K * Nout) return;
    int k = idx / Nout, n = idx - k * Nout;
    d_Wh[(size_t)(rowOff + n) * K + k] = __float2half(W[idx]);
}

__global__ void k_convAtt(const float* __restrict__ Wm, const float* __restrict__ att,
                          const float* __restrict__ bm, int K, int C, int rowA) {
    int t = threadIdx.x;
    int NC = 4 * C;
    if (t < K * 4) {
        int k = t >> 2, h = t & 3;
        float s = 0.f;
        for (int c = 0; c < C; c++) s += Wm[(size_t)k * NC + h * C + c] * att[h * C + c];
        d_Wh[(size_t)(rowA + h) * K + k] = __float2half(s);
    }
    if (t < 4) {
        float s = 0.f;
        for (int c = 0; c < C; c++) s += bm[t * C + c] * att[t * C + c];
        d_batt[t] = s;
    }
}

// ---------------- fp16 MMA GEMM (BK=32 loop, 16KB tiles) ----------------
__device__ __forceinline__ uint32_t swz_off(int row, int c16) {
    return (uint32_t)((row << 6) + (((c16 ^ ((row >> 1) & 3)) & 3) << 4));
}

template <int K>
__global__ __launch_bounds__(256) void k_hgemm(
    const float* __restrict__ A,
    const float* __restrict__ biasM, const float* __restrict__ biasS,
    uint8_t* __restrict__ M8, float* __restrict__ S, float* __restrict__ aN,
    int rowOff, int Mrows, int Nout, int NsplitM, int NsplitA, int strideM, int strideS)
{
    __shared__ __align__(16) char As[128 * 64];
    __shared__ __align__(16) char Bs[128 * 64];
    int tid = threadIdx.x;
    int wid = tid >> 5, lane = tid & 31;
    int r0 = rowOff + blockIdx.x * 128;
    int n0 = blockIdx.y * 128;
    int wm = (wid & 3) * 32;
    int wn = (wid >> 2) * 64;

    uint32_t AsAddr = (uint32_t)__cvta_generic_to_shared(As);
    uint32_t BsAddr = (uint32_t)__cvta_generic_to_shared(Bs);

    float acc[2][8][4];
    #pragma unroll
    for (int i = 0; i < 2; i++)
        #pragma unroll
        for (int j = 0; j < 8; j++)
            #pragma unroll
            for (int q = 0; q < 4; q++) acc[i][j][q] = 0.f;

    #pragma unroll
    for (int kb = 0; kb < K; kb += 32) {
        #pragma unroll
        for (int it = 0; it < 2; it++) {
            int linear = tid + it * 256;
            int row = linear >> 2;
            int c8 = (linear & 3) << 3;
            int gr = r0 + row;
            float v[8];
            if (gr < Mrows) {
                float4 u0 = *(const float4*)(A + (size_t)gr * K + kb + c8);
                float4 u1 = *(const float4*)(A + (size_t)gr * K + kb + c8 + 4);
                v[0] = u0.x; v[1] = u0.y; v[2] = u0.z; v[3] = u0.w;
                v[4] = u1.x; v[5] = u1.y; v[6] = u1.z; v[7] = u1.w;
            } else {
                #pragma unroll
                for (int j = 0; j < 8; j++) v[j] = 0.f;
            }
            uint32_t pk[4];
            #pragma unroll
            for (int j = 0; j < 4; j++) {
                __half2 h = __floats2half2_rn(v[2 * j], v[2 * j + 1]);
                pk[j] = *(uint32_t*)&h;
            }
            *(uint4*)(As + swz_off(row, c8 >> 3)) = make_uint4(pk[0], pk[1], pk[2], pk[3]);
        }
        #pragma unroll
        for (int it = 0; it < 2; it++) {
            int linear = tid + it * 256;
            int row = linear >> 2;
            int c8 = (linear & 3) << 3;
            int gn = n0 + row;
            uint4 v = make_uint4(0u, 0u, 0u, 0u);
            if (gn < Nout)
                v = *(const uint4*)(d_Wh + (size_t)gn * K + kb + c8);
            *(uint4*)(Bs + swz_off(row, c8 >> 3)) = v;
        }
        __syncthreads();

        #pragma unroll
        for (int ks = 0; ks < 32; ks += 16) {
            uint32_t aF[2][4], bF[8][2];
            int q = lane >> 3;
            #pragma unroll
            for (int mt = 0; mt < 2; mt++) {
                int row = wm + mt * 16 + ((q & 1) << 3) + (lane & 7);
                int c16 = (ks >> 3) + (q >> 1);
                uint32_t addr = AsAddr + swz_off(row, c16);
                asm volatile("ldmatrix.sync.aligned.m8n8.x4.shared.b16 {%0,%1,%2,%3}, [%4];"
                    : "=r"(aF[mt][0]), "=r"(aF[mt][1]), "=r"(aF[mt][2]), "=r"(aF[mt][3])
                    : "r"(addr));
            }
            #pragma unroll
            for (int np = 0; np < 4; np++) {
                int row = wn + np * 16 + ((q >> 1) << 3) + (lane & 7);
                int c16 = (ks >> 3) + (q & 1);
                uint32_t addr = BsAddr + swz_off(row, c16);
                asm volatile("ldmatrix.sync.aligned.m8n8.x4.shared.b16 {%0,%1,%2,%3}, [%4];"
                    : "=r"(bF[2 * np][0]), "=r"(bF[2 * np][1]),
                      "=r"(bF[2 * np + 1][0]), "=r"(bF[2 * np + 1][1])
                    : "r"(addr));
            }
            #pragma unroll
            for (int mt = 0; mt < 2; mt++)
                #pragma unroll
                for (int nt = 0; nt < 8; nt++) {
                    asm volatile(
                        "mma.sync.aligned.m16n8k16.row.col.f32.f16.f16.f32 "
                        "{%0,%1,%2,%3}, {%4,%5,%6,%7}, {%8,%9}, {%0,%1,%2,%3};"
                        : "+f"(acc[mt][nt][0]), "+f"(acc[mt][nt][1]),
                          "+f"(acc[mt][nt][2]), "+f"(acc[mt][nt][3])
                        : "r"(aF[mt][0]), "r"(aF[mt][1]), "r"(aF[mt][2]), "r"(aF[mt][3]),
                          "r"(bF[nt][0]), "r"(bF[nt][1]));
                }
        }
        __syncthreads();
    }

    #pragma unroll
    for (int mt = 0; mt < 2; mt++) {
        int m = r0 + wm + mt * 16 + (lane >> 2);
        #pragma unroll
        for (int nt = 0; nt < 8; nt++) {
            int n = n0 + wn + nt * 8 + (lane & 3) * 2;
            if (n >= Nout) continue;
            if (n < NsplitM) {
                float2 bb = *(const float2*)(biasM + n);
                #pragma unroll
                for (int hf = 0; hf < 2; hf++) {
                    int mr = m + hf * 8;
                    if (mr < Mrows) {
                        uint16_t o = f32x2_to_e4m3(acc[mt][nt][2 * hf + 1] + bb.y,
                                                   acc[mt][nt][2 * hf] + bb.x);
                        *(uint16_t*)(M8 + (size_t)mr * strideM + n) = o;
                    }
                }
            } else if (n < NsplitA) {
                int nn = n - NsplitM;
                float2 bb = *(const float2*)(biasS + nn);
                #pragma unroll
                for (int hf = 0; hf < 2; hf++) {
                    int mr = m + hf * 8;
                    if (mr < Mrows) {
                        float2 o = make_float2(acc[mt][nt][2 * hf] + bb.x,
                                               acc[mt][nt][2 * hf + 1] + bb.y);
                        *(float2*)(S + (size_t)mr * strideS + nn) = o;
                    }
                }
            } else {
                int nn = n - NsplitA;
                float2 bb = *(const float2*)(d_batt + nn);
                #pragma unroll
                for (int hf = 0; hf < 2; hf++) {
                    int mr = m + hf * 8;
                    if (mr < Mrows) {
                        float vx = acc[mt][nt][2 * hf] + bb.x;
                        float vy = acc[mt][nt][2 * hf + 1] + bb.y;
                        vx = (vx > 0.f) ? vx : 0.2f * vx;
                        vy = (vy > 0.f) ? vy : 0.2f * vy;
                        *(float2*)(aN + (size_t)mr * 4 + nn) = make_float2(vx, vy);
                    }
                }
            }
        }
    }
}

// ---------------- aggregation (R9 inner loop; parameterized buffers + node range) ----------------
template <int C>
__global__ __launch_bounds__(256) void k_agg(
    const uint8_t* __restrict__ M8, const float* __restrict__ aN,
    const float* __restrict__ resid, float* __restrict__ out,
    int nodeBeg, int nodeEnd)
{
    const int HC = 4 * C;
    const int PL = HC / 32;
    const int NW = PL / 4;
    __shared__ float wsh[8][8][4];
    __shared__ int ssh[8][8];
    int gw = nodeBeg + ((blockIdx.x * blockDim.x + threadIdx.x) >> 5);
    int lane = threadIdx.x & 31;
    int wId = threadIdx.x >> 5;
    if (gw >= nodeEnd) return;
    int start = d_rowptr[gw], end = d_rowptr[gw + 1];

    float m0 = -INFINITY, m1 = -INFINITY, m2 = -INFINITY, m3 = -INFINITY;
    for (int i = start + lane; i < end; i += 32) {
        int s = d_csrsrc[i];
        float4 a = *(const float4*)(aN + (size_t)s * 4);
        m0 = fmaxf(m0, a.x); m1 = fmaxf(m1, a.y);
        m2 = fmaxf(m2, a.z); m3 = fmaxf(m3, a.w);
    }
    #pragma unroll
    for (int off = 16; off > 0; off >>= 1) {
        m0 = fmaxf(m0, __shfl_xor_sync(0xffffffffu, m0, off));
        m1 = fmaxf(m1, __shfl_xor_sync(0xffffffffu, m1, off));
        m2 = fmaxf(m2, __shfl_xor_sync(0xffffffffu, m2, off));
        m3 = fmaxf(m3, __shfl_xor_sync(0xffffffffu, m3, off));
    }
    int h = lane >> 3;
    int hh = lane & 3;
    float mhh = (hh == 0) ? m0 : (hh == 1) ? m1 : (hh == 2) ? m2 : m3;

    __half2 acc2[NW * 2];
    #pragma unroll
    for (int j = 0; j < NW * 2; j++) acc2[j] = __float2half2_rn(0.f);
    float denL = 0.f;
    int ei = lane >> 2;

    for (int base = start; base < end; base += 8) {
        int ne = end - base;
        if (ne > 8) ne = 8;
        if (ei < ne) {
            int sl = d_csrsrc[base + ei];
            float a = aN[(size_t)sl * 4 + hh];
            float wl = expf(a - mhh);
            denL += wl;
            wsh[wId][ei][hh] = wl;
            if (hh == 0) ssh[wId][ei] = sl;
        }
        __syncwarp();
        for (int e = 0; e < ne; e++) {
            int s = ssh[wId][e];
            __half2 wh = __float2half2_rn(wsh[wId][e][h]);
            const uint32_t* rb = (const uint32_t*)(M8 + (size_t)s * HC + lane * PL);
            uint32_t wv[NW];
            #pragma unroll
            for (int i = 0; i < NW; i++) wv[i] = rb[i];
            #pragma unroll
            for (int i = 0; i < NW; i++) {
                acc2[2 * i] = __hfma2(e4m3x2_to_h2((uint16_t)wv[i]), wh, acc2[2 * i]);
                acc2[2 * i + 1] = __hfma2(e4m3x2_to_h2((uint16_t)(wv[i] >> 16)), wh, acc2[2 * i + 1]);
            }
        }
        __syncwarp();
    }
    denL += __shfl_xor_sync(0xffffffffu, denL, 4);
    denL += __shfl_xor_sync(0xffffffffu, denL, 8);
    denL += __shfl_xor_sync(0xffffffffu, denL, 16);
    float den = __shfl_sync(0xffffffffu, denL, h);
    float inv = 0.25f / (den + 1e-16f);

    float acc[PL];
    #pragma unroll
    for (int j = 0; j < NW * 2; j++) {
        float2 t = __half22float2(acc2[j]);
        acc[2 * j] = t.x;
        acc[2 * j + 1] = t.y;
    }
    #pragma unroll
    for (int j = 0; j < PL; j++) {
        float v = acc[j] * inv;
        v += __shfl_xor_sync(0xffffffffu, v, 8);
        v += __shfl_xor_sync(0xffffffffu, v, 16);
        acc[j] = v;
    }
    if (lane < 8) {
        int col = lane * PL;
        #pragma unroll
        for (int q = 0; q < PL / 4; q++) {
            float4 r = *(const float4*)(resid + (size_t)gw * C + col + q * 4);
            float4 o;
            o.x = acc[q * 4 + 0] + r.x;
            o.y = acc[q * 4 + 1] + r.y;
            o.z = acc[q * 4 + 2] + r.z;
            o.w = acc[q * 4 + 3] + r.w;
            *(float4*)(out + (size_t)gw * C + col + q * 4) = o;
        }
    }
}

// ---------------- graph boundaries ----------------
__global__ void k_gstart(const int* __restrict__ batch) {
    int i = blockIdx.x * blockDim.x + threadIdx.x;
    if (i >= NN) return;
    int b = batch[i];
    int bp = (i == 0) ? -1 : batch[i - 1];
    for (int g = bp + 1; g <= b; g++) d_gstart[g] = i;
    if (i == NN - 1)
        for (int g = b + 1; g <= NG; g++) d_gstart[g] = NN;
}

// ---------------- global mean pool ----------------
__global__ void k_pool() {
    int g = blockIdx.x;
    int start = d_gstart[g], end = d_gstart[g + 1];
    int c = threadIdx.x & 63;
    int stripe = threadIdx.x >> 6;
    float acc = 0.f;
    for (int r = start + stripe; r < end; r += 4) acc += d_h3[(size_t)r * 64 + c];
    __shared__ float sh[256];
    sh[threadIdx.x] = acc;
    __syncthreads();
    if (stripe == 0) {
        float v = sh[c] + sh[c + 64] + sh[c + 128] + sh[c + 192];
        float cnt = (float)(end - start);
        d_pooled[g * 64 + c] = v / fmaxf(cnt, 1.0f);
    }
}

// ---------------- classifier + log_softmax ----------------
__global__ void k_fc(const float* __restrict__ Wfc, const float* __restrict__ bfc,
                     float* __restrict__ out) {
    int g = threadIdx.x;
    if (g >= NG) return;
    float logits[10];
    #pragma unroll
    for (int o = 0; o < 10; o++) {
        float s = bfc[o];
        for (int c = 0; c < 64; c++) s += d_pooled[g * 64 + c] * Wfc[c * 10 + o];
        logits[o] = s;
    }
    float mx = logits[0];
    #pragma unroll
    for (int o = 1; o < 10; o++) mx = fmaxf(mx, logits[o]);
    float se = 0.f;
    #pragma unroll
    for (int o = 0; o < 10; o++) se += expf(logits[o] - mx);
    float lse = mx + logf(se);
    #pragma unroll
    for (int o = 0; o < 10; o++) out[g * 10 + o] = logits[o] - lse;
}

// ---------------- launch: dual-stream, half-split pipelined layers ----------------
extern "C" void kernel_launch(void* const* d_in, const int* in_sizes, int n_in,
                              void* d_out, int out_size) {
    const float* x    = (const float*)d_in[0];
    const int* edge   = (const int*)d_in[1];
    const int* batch  = (const int*)d_in[2];
    const float* Wm1  = (const float*)d_in[3];
    const float* bm1  = (const float*)d_in[4];
    const float* att1 = (const float*)d_in[5];
    const float* Ws1  = (const float*)d_in[6];
    const float* bs1  = (const float*)d_in[7];
    const float* Wm2  = (const float*)d_in[8];
    const float* bm2  = (const float*)d_in[9];
    const float* att2 = (const float*)d_in[10];
    const float* Wm3  = (const float*)d_in[11];
    const float* bm3  = (const float*)d_in[12];
    const float* att3 = (const float*)d_in[13];
    const float* Ws3  = (const float*)d_in[14];
    const float* bs3  = (const float*)d_in[15];
    const float* Wfc  = (const float*)d_in[16];
    const float* bfc  = (const float*)d_in[17];
    float* out = (float*)d_out;

    const int* srcp = edge;
    const int* dstp = edge + NE;

    float *S, *h1, *h2, *h3, *aNA, *aNB;
    uint8_t *M8A, *M8B;
    int* degp;
    cudaGetSymbolAddress((void**)&S, d_S);
    cudaGetSymbolAddress((void**)&h1, d_h1);
    cudaGetSymbolAddress((void**)&h2, d_h2);
    cudaGetSymbolAddress((void**)&h3, d_h3);
    cudaGetSymbolAddress((void**)&M8A, d_M8A);
    cudaGetSymbolAddress((void**)&M8B, d_M8B);
    cudaGetSymbolAddress((void**)&aNA, d_aNA);
    cudaGetSymbolAddress((void**)&aNB, d_aNB);
    cudaGetSymbolAddress((void**)&degp, d_deg);

    static cudaStream_t s2 = nullptr;
    static cudaEvent_t evFork, evG1, evC2, evA1h0, evG2h0, evG2h1, evC3, evA2h0, evG3h0, evGst;
    if (!s2) {
        cudaStreamCreateWithFlags(&s2, cudaStreamNonBlocking);
        cudaEventCreateWithFlags(&evFork, cudaEventDisableTiming);
        cudaEventCreateWithFlags(&evG1, cudaEventDisableTiming);
        cudaEventCreateWithFlags(&evC2, cudaEventDisableTiming);
        cudaEventCreateWithFlags(&evA1h0, cudaEventDisableTiming);
        cudaEventCreateWithFlags(&evG2h0, cudaEventDisableTiming);
        cudaEventCreateWithFlags(&evG2h1, cudaEventDisableTiming);
        cudaEventCreateWithFlags(&evC3, cudaEventDisableTiming);
        cudaEventCreateWithFlags(&evA2h0, cudaEventDisableTiming);
        cudaEventCreateWithFlags(&evG3h0, cudaEventDisableTiming);
        cudaEventCreateWithFlags(&evGst, cudaEventDisableTiming);
    }

    const int TB = 256;
    const int nodeBlocks = (NN + TB - 1) / TB;
    const int edgeBlocks = (NE + TB - 1) / TB;
    const int warpNodeBlocks = (NN * 32 + TB - 1) / TB;
    const int rowBlocks = (NN + 127) / 128;           // 391
    const int rbH0 = NS / 128;                        // 196
    const int rbH1 = (NN - NS + 127) / 128;           // 195
    const int aggH0 = (NS * 32 + TB - 1) / TB;        // 3136
    const int aggH1 = ((NN - NS) * 32 + TB - 1) / TB; // 3114
    cudaStream_t s0 = 0;

    cudaEventRecord(evFork, s0);
    cudaStreamWaitEvent(s2, evFork, 0);

    // ---- branch A (s0): CSR build ----
    cudaMemsetAsync(degp, 0, NN * sizeof(int), s0);
    k_degree<<<edgeBlocks, TB, 0, s0>>>(dstp);
    k_scan<<<1, 1024, 0, s0>>>();
    k_scatter<<<edgeBlocks, TB, 0, s0>>>(srcp, dstp);
    k_sortw<<<warpNodeBlocks, TB, 0, s0>>>();

    // ---- branch B (s2): gstart + layer-1 weights + GEMM1 (full), writes M8A/aNA/S ----
    k_gstart<<<nodeBlocks, TB, 0, s2>>>(batch);
    cudaEventRecord(evGst, s2);
    k_convW<<<(64 * 384 + TB - 1) / TB, TB, 0, s2>>>(Wm1, 64, 384, 0);
    k_convW<<<(64 * 96 + TB - 1) / TB, TB, 0, s2>>>(Ws1, 64, 96, 384);
    k_convAtt<<<1, 512, 0, s2>>>(Wm1, att1, bm1, 64, 96, 480);
    k_hgemm<64><<<dim3(rowBlocks, 4), TB, 0, s2>>>(x, bm1, bs1, M8A, S, aNA, 0, NN, 484, 384, 480, 384, 96);
    cudaEventRecord(evG1, s2);
    // layer-2 weights (overlap agg1)
    k_convW<<<(96 * 384 + TB - 1) / TB, TB, 0, s2>>>(Wm2, 96, 384, 0);
    k_convAtt<<<1, 512, 0, s2>>>(Wm2, att2, bm2, 96, 96, 384);
    cudaEventRecord(evC2, s2);

    // ---- agg1 h0 (s0): needs CSR (order) + GEMM1 ----
    cudaStreamWaitEvent(s0, evG1, 0);
    k_agg<96><<<aggH0, TB, 0, s0>>>(M8A, aNA, S, h1, 0, NS);
    cudaEventRecord(evA1h0, s0);
    // agg1 h1 (s0) concurrent with gemm2 h0 (s2)
    k_agg<96><<<aggH1, TB, 0, s0>>>(M8A, aNA, S, h1, NS, NN);

    // ---- gemm2 h0 on s2: needs agg1 h0 + conv2 (s2 order); writes M8B/aNB ----
    cudaStreamWaitEvent(s2, evA1h0, 0);
    k_hgemm<96><<<dim3(rbH0, 4), TB, 0, s2>>>(h1, bm2, bm2, M8B, S, aNB, 0, NN, 388, 384, 384, 384, 96);
    cudaEventRecord(evG2h0, s2);

    // ---- gemm2 h1 on s0 (after agg1 h1 in order; needs conv2) ----
    cudaStreamWaitEvent(s0, evC2, 0);
    k_hgemm<96><<<dim3(rbH1, 4), TB, 0, s0>>>(h1, bm2, bm2, M8B, S, aNB, NS, NN, 388, 384, 384, 384, 96);
    cudaEventRecord(evG2h1, s0);

    // ---- layer-3 weights on s2: need gemm2 fully done reading d_Wh ----
    cudaStreamWaitEvent(s2, evG2h1, 0);
    k_convW<<<(96 * 256 + TB - 1) / TB, TB, 0, s2>>>(Wm3, 96, 256, 0);
    k_convW<<<(96 * 64 + TB - 1) / TB, TB, 0, s2>>>(Ws3, 96, 64, 256);
    k_convAtt<<<1, 512, 0, s2>>>(Wm3, att3, bm3, 96, 64, 320);
    cudaEventRecord(evC3, s2);

    // ---- agg2 h0 (s0): needs gemm2 h0 (event) + h1 (order) ----
    cudaStreamWaitEvent(s0, evG2h0, 0);
    k_agg<96><<<aggH0, TB, 0, s0>>>(M8B, aNB, h1, h2, 0, NS);
    cudaEventRecord(evA2h0, s0);
    // agg2 h1 (s0) concurrent with gemm3 h0 (s2)
    k_agg<96><<<aggH1, TB, 0, s0>>>(M8B, aNB, h1, h2, NS, NN);

    // ---- gemm3 h0 on s2: needs agg2 h0 + conv3 (s2 order); writes M8A/aNA/S ----
    cudaStreamWaitEvent(s2, evA2h0, 0);
    k_hgemm<96><<<dim3(rbH0, 3), TB, 0, s2>>>(h2, bm3, bs3, M8A, S, aNA, 0, NN, 324, 256, 320, 256, 64);
    cudaEventRecord(evG3h0, s2);

    // ---- gemm3 h1 on s0 (after agg2 h1 in order; needs conv3) ----
    cudaStreamWaitEvent(s0, evC3, 0);
    k_hgemm<96><<<dim3(rbH1, 3), TB, 0, s0>>>(h2, bm3, bs3, M8A, S, aNA, NS, NN, 324, 256, 320, 256, 64);

    // ---- agg3 (s0): needs gemm3 h0 (event) + h1 (order) ----
    cudaStreamWaitEvent(s0, evG3h0, 0);
    k_agg<64><<<warpNodeBlocks, TB, 0, s0>>>(M8A, aNA, S, h3, 0, NN);

    // ---- pool + classifier ----
    cudaStreamWaitEvent(s0, evGst, 0);
    k_pool<<<NG, 256, 0, s0>>>();
    k_fc<<<1, 64, 0, s0>>>(Wfc, bfc, out);
}

// round 15
// speedup vs baseline: 1.4292x; 1.0792x over previous
#include <cuda_runtime.h>
#include <cuda_fp16.h>
#include <math.h>
#include <stdint.h>
#include <limits.h>

#define NN 50000
#define NE 400000
#define NG 64
#define NS 25088   // half split: 196 row-blocks of 128

// ---------------- static scratch (no allocations allowed) ----------------
__device__ __align__(16) uint8_t d_M8A[(size_t)NN * 384];
__device__ __align__(16) uint8_t d_M8B[(size_t)NN * 384];
__device__ __align__(16) float d_aNA[(size_t)NN * 4];
__device__ __align__(16) float d_aNB[(size_t)NN * 4];
__device__ float d_h1[(size_t)NN * 96];
__device__ float d_h2[(size_t)NN * 96];
__device__ float d_h3[(size_t)NN * 64];
__device__ float d_S[(size_t)NN * 96];
__device__ int d_deg[NN];
__device__ int d_rowptr[NN + 1];
__device__ int d_cursor[NN];
__device__ int d_csrsrc[NE];
__device__ int d_gstart[NG + 1];
__device__ float d_pooled[NG * 64];
__device__ __align__(16) __half d_Wh[(size_t)512 * 96];
__device__ __align__(16) float d_batt[4];

// ---------------- fp8 helpers ----------------
__device__ __forceinline__ uint16_t f32x2_to_e4m3(float hi, float lo) {
    uint16_t o;
    asm("cvt.rn.satfinite.e4m3x2.f32 %0, %1, %2;" : "=h"(o) : "f"(hi), "f"(lo));
    return o;
}
__device__ __forceinline__ __half2 e4m3x2_to_h2(uint16_t v) {
    uint32_t r;
    asm("cvt.rn.f16x2.e4m3x2 %0, %1;" : "=r"(r) : "h"(v));
    return *(__half2*)&r;
}

// ---------------- CSR build ----------------
__global__ void k_degree(const int* __restrict__ dst) {
    int i = blockIdx.x * blockDim.x + threadIdx.x;
    if (i < NE) atomicAdd(&d_deg[dst[i]], 1);
}

__global__ void k_scan() {
    __shared__ int wsum[32];
    __shared__ int carrySh;
    int tid = threadIdx.x;
    int lane = tid & 31, w = tid >> 5;
    if (tid == 0) carrySh = 0;
    __syncthreads();
    for (int base = 0; base < NN; base += 1024) {
        int i = base + tid;
        int v = (i < NN) ? d_deg[i] : 0;
        int incl = v;
        #pragma unroll
        for (int off = 1; off < 32; off <<= 1) {
            int t = __shfl_up_sync(0xffffffffu, incl, off);
            if (lane >= off) incl += t;
        }
        if (lane == 31) wsum[w] = incl;
        __syncthreads();
        if (w == 0) {
            int s = wsum[lane];
            #pragma unroll
            for (int off = 1; off < 32; off <<= 1) {
                int t = __shfl_up_sync(0xffffffffu, s, off);
                if (lane >= off) s += t;
            }
            wsum[lane] = s;
        }
        __syncthreads();
        int woff = (w > 0) ? wsum[w - 1] : 0;
        int carry = carrySh;
        int total = wsum[31];
        __syncthreads();
        if (i < NN) {
            int ex = carry + woff + incl - v;
            d_rowptr[i] = ex;
            d_cursor[i] = ex;
        }
        if (tid == 0) carrySh = carry + total;
        __syncthreads();
    }
    if (tid == 0) d_rowptr[NN] = carrySh;
}

__global__ void k_scatter(const int* __restrict__ src, const int* __restrict__ dst) {
    int i = blockIdx.x * blockDim.x + threadIdx.x;
    if (i < NE) {
        int p = atomicAdd(&d_cursor[dst[i]], 1);
        d_csrsrc[p] = src[i];
    }
}

__global__ void k_sortw() {
    int gw = (blockIdx.x * blockDim.x + threadIdx.x) >> 5;
    int lane = threadIdx.x & 31;
    if (gw >= NN) return;
    int s = d_rowptr[gw], e = d_rowptr[gw + 1];
    int d = e - s;
    if (d <= 1) return;
    if (d <= 32) {
        int v = (lane < d) ? d_csrsrc[s + lane] : INT_MAX;
        #pragma unroll
        for (int k = 2; k <= 32; k <<= 1) {
            #pragma unroll
            for (int j = k >> 1; j > 0; j >>= 1) {
                int other = __shfl_xor_sync(0xffffffffu, v, j);
                bool dirUp = ((lane & k) == 0);
                bool lower = ((lane & j) == 0);
                int mn = min(v, other), mx = max(v, other);
                v = (dirUp == lower) ? mn : mx;
            }
        }
        if (lane < d) d_csrsrc[s + lane] = v;
    } else if (lane == 0) {
        for (int i = s + 1; i < e; i++) {
            int v = d_csrsrc[i];
            int j = i - 1;
            while (j >= s && d_csrsrc[j] > v) {
                d_csrsrc[j + 1] = d_csrsrc[j];
                j--;
            }
            d_csrsrc[j + 1] = v;
        }
    }
}

// ---------------- weight conversions ----------------
__global__ void k_convW(const float* __restrict__ W, int K, int Nout, int rowOff) {
    int idx = blockIdx.x * blockDim.x + threadIdx.x;
    if (idx >= K * Nout) return;
    int k = idx / Nout, n = idx - k * Nout;
    d_Wh[(size_t)(rowOff + n) * K + k] = __float2half(W[idx]);
}

__global__ void k_convAtt(const float* __restrict__ Wm, const float* __restrict__ att,
                          const float* __restrict__ bm, int K, int C, int rowA) {
    int t = threadIdx.x;
    int NC = 4 * C;
    if (t < K * 4) {
        int k = t >> 2, h = t & 3;
        float s = 0.f;
        for (int c = 0; c < C; c++) s += Wm[(size_t)k * NC + h * C + c] * att[h * C + c];
        d_Wh[(size_t)(rowA + h) * K + k] = __float2half(s);
    }
    if (t < 4) {
        float s = 0.f;
        for (int c = 0; c < C; c++) s += bm[t * C + c] * att[t * C + c];
        d_batt[t] = s;
    }
}

// ---------------- fp16 MMA GEMM (BK=32 loop, 16KB tiles) ----------------
__device__ __forceinline__ uint32_t swz_off(int row, int c16) {
    return (uint32_t)((row << 6) + (((c16 ^ ((row >> 1) & 3)) & 3) << 4));
}

template <int K>
__global__ __launch_bounds__(256) void k_hgemm(
    const float* __restrict__ A,
    const float* __restrict__ biasM, const float* __restrict__ biasS,
    uint8_t* __restrict__ M8, float* __restrict__ S, float* __restrict__ aN,
    int rowOff, int Mrows, int Nout, int NsplitM, int NsplitA, int strideM, int strideS)
{
    __shared__ __align__(16) char As[128 * 64];
    __shared__ __align__(16) char Bs[128 * 64];
    int tid = threadIdx.x;
    int wid = tid >> 5, lane = tid & 31;
    int r0 = rowOff + blockIdx.x * 128;
    int n0 = blockIdx.y * 128;
    int wm = (wid & 3) * 32;
    int wn = (wid >> 2) * 64;

    uint32_t AsAddr = (uint32_t)__cvta_generic_to_shared(As);
    uint32_t BsAddr = (uint32_t)__cvta_generic_to_shared(Bs);

    float acc[2][8][4];
    #pragma unroll
    for (int i = 0; i < 2; i++)
        #pragma unroll
        for (int j = 0; j < 8; j++)
            #pragma unroll
            for (int q = 0; q < 4; q++) acc[i][j][q] = 0.f;

    #pragma unroll
    for (int kb = 0; kb < K; kb += 32) {
        #pragma unroll
        for (int it = 0; it < 2; it++) {
            int linear = tid + it * 256;
            int row = linear >> 2;
            int c8 = (linear & 3) << 3;
            int gr = r0 + row;
            float v[8];
            if (gr < Mrows) {
                float4 u0 = *(const float4*)(A + (size_t)gr * K + kb + c8);
                float4 u1 = *(const float4*)(A + (size_t)gr * K + kb + c8 + 4);
                v[0] = u0.x; v[1] = u0.y; v[2] = u0.z; v[3] = u0.w;
                v[4] = u1.x; v[5] = u1.y; v[6] = u1.z; v[7] = u1.w;
            } else {
                #pragma unroll
                for (int j = 0; j < 8; j++) v[j] = 0.f;
            }
            uint32_t pk[4];
            #pragma unroll
            for (int j = 0; j < 4; j++) {
                __half2 h = __floats2half2_rn(v[2 * j], v[2 * j + 1]);
                pk[j] = *(uint32_t*)&h;
            }
            *(uint4*)(As + swz_off(row, c8 >> 3)) = make_uint4(pk[0], pk[1], pk[2], pk[3]);
        }
        #pragma unroll
        for (int it = 0; it < 2; it++) {
            int linear = tid + it * 256;
            int row = linear >> 2;
            int c8 = (linear & 3) << 3;
            int gn = n0 + row;
            uint4 v = make_uint4(0u, 0u, 0u, 0u);
            if (gn < Nout)
                v = *(const uint4*)(d_Wh + (size_t)gn * K + kb + c8);
            *(uint4*)(Bs + swz_off(row, c8 >> 3)) = v;
        }
        __syncthreads();

        #pragma unroll
        for (int ks = 0; ks < 32; ks += 16) {
            uint32_t aF[2][4], bF[8][2];
            int q = lane >> 3;
            #pragma unroll
            for (int mt = 0; mt < 2; mt++) {
                int row = wm + mt * 16 + ((q & 1) << 3) + (lane & 7);
                int c16 = (ks >> 3) + (q >> 1);
                uint32_t addr = AsAddr + swz_off(row, c16);
                asm volatile("ldmatrix.sync.aligned.m8n8.x4.shared.b16 {%0,%1,%2,%3}, [%4];"
                    : "=r"(aF[mt][0]), "=r"(aF[mt][1]), "=r"(aF[mt][2]), "=r"(aF[mt][3])
                    : "r"(addr));
            }
            #pragma unroll
            for (int np = 0; np < 4; np++) {
                int row = wn + np * 16 + ((q >> 1) << 3) + (lane & 7);
                int c16 = (ks >> 3) + (q & 1);
                uint32_t addr = BsAddr + swz_off(row, c16);
                asm volatile("ldmatrix.sync.aligned.m8n8.x4.shared.b16 {%0,%1,%2,%3}, [%4];"
                    : "=r"(bF[2 * np][0]), "=r"(bF[2 * np][1]),
                      "=r"(bF[2 * np + 1][0]), "=r"(bF[2 * np + 1][1])
                    : "r"(addr));
            }
            #pragma unroll
            for (int mt = 0; mt < 2; mt++)
                #pragma unroll
                for (int nt = 0; nt < 8; nt++) {
                    asm volatile(
                        "mma.sync.aligned.m16n8k16.row.col.f32.f16.f16.f32 "
                        "{%0,%1,%2,%3}, {%4,%5,%6,%7}, {%8,%9}, {%0,%1,%2,%3};"
                        : "+f"(acc[mt][nt][0]), "+f"(acc[mt][nt][1]),
                          "+f"(acc[mt][nt][2]), "+f"(acc[mt][nt][3])
                        : "r"(aF[mt][0]), "r"(aF[mt][1]), "r"(aF[mt][2]), "r"(aF[mt][3]),
                          "r"(bF[nt][0]), "r"(bF[nt][1]));
                }
        }
        __syncthreads();
    }

    #pragma unroll
    for (int mt = 0; mt < 2; mt++) {
        int m = r0 + wm + mt * 16 + (lane >> 2);
        #pragma unroll
        for (int nt = 0; nt < 8; nt++) {
            int n = n0 + wn + nt * 8 + (lane & 3) * 2;
            if (n >= Nout) continue;
            if (n < NsplitM) {
                float2 bb = *(const float2*)(biasM + n);
                #pragma unroll
                for (int hf = 0; hf < 2; hf++) {
                    int mr = m + hf * 8;
                    if (mr < Mrows) {
                        uint16_t o = f32x2_to_e4m3(acc[mt][nt][2 * hf + 1] + bb.y,
                                                   acc[mt][nt][2 * hf] + bb.x);
                        *(uint16_t*)(M8 + (size_t)mr * strideM + n) = o;
                    }
                }
            } else if (n < NsplitA) {
                int nn = n - NsplitM;
                float2 bb = *(const float2*)(biasS + nn);
                #pragma unroll
                for (int hf = 0; hf < 2; hf++) {
                    int mr = m + hf * 8;
                    if (mr < Mrows) {
                        float2 o = make_float2(acc[mt][nt][2 * hf] + bb.x,
                                               acc[mt][nt][2 * hf + 1] + bb.y);
                        *(float2*)(S + (size_t)mr * strideS + nn) = o;
                    }
                }
            } else {
                int nn = n - NsplitA;
                float2 bb = *(const float2*)(d_batt + nn);
                #pragma unroll
                for (int hf = 0; hf < 2; hf++) {
                    int mr = m + hf * 8;
                    if (mr < Mrows) {
                        float vx = acc[mt][nt][2 * hf] + bb.x;
                        float vy = acc[mt][nt][2 * hf + 1] + bb.y;
                        vx = (vx > 0.f) ? vx : 0.2f * vx;
                        vy = (vy > 0.f) ? vy : 0.2f * vy;
                        *(float2*)(aN + (size_t)mr * 4 + nn) = make_float2(vx, vy);
                    }
                }
            }
        }
    }
}

// ---------------- aggregation: no max-pass (logits are small), __expf weights ----------------
template <int C>
__global__ __launch_bounds__(256) void k_agg(
    const uint8_t* __restrict__ M8, const float* __restrict__ aN,
    const float* __restrict__ resid, float* __restrict__ out,
    int nodeBeg, int nodeEnd)
{
    const int HC = 4 * C;
    const int PL = HC / 32;
    const int NW = PL / 4;
    __shared__ float wsh[8][8][4];
    __shared__ int ssh[8][8];
    int gw = nodeBeg + ((blockIdx.x * blockDim.x + threadIdx.x) >> 5);
    int lane = threadIdx.x & 31;
    int wId = threadIdx.x >> 5;
    if (gw >= nodeEnd) return;
    int start = d_rowptr[gw], end = d_rowptr[gw + 1];

    int h = lane >> 3;
    int hh = lane & 3;

    __half2 acc2[NW * 2];
    #pragma unroll
    for (int j = 0; j < NW * 2; j++) acc2[j] = __float2half2_rn(0.f);
    float denL = 0.f;
    int ei = lane >> 2;

    for (int base = start; base < end; base += 8) {
        int ne = end - base;
        if (ne > 8) ne = 8;
        if (ei < ne) {
            int sl = d_csrsrc[base + ei];
            float a = aN[(size_t)sl * 4 + hh];
            float wl = __expf(a);
            denL += wl;
            wsh[wId][ei][hh] = wl;
            if (hh == 0) ssh[wId][ei] = sl;
        }
        __syncwarp();
        for (int e = 0; e < ne; e++) {
            int s = ssh[wId][e];
            __half2 wh = __float2half2_rn(wsh[wId][e][h]);
            const uint32_t* rb = (const uint32_t*)(M8 + (size_t)s * HC + lane * PL);
            uint32_t wv[NW];
            #pragma unroll
            for (int i = 0; i < NW; i++) wv[i] = rb[i];
            #pragma unroll
            for (int i = 0; i < NW; i++) {
                acc2[2 * i] = __hfma2(e4m3x2_to_h2((uint16_t)wv[i]), wh, acc2[2 * i]);
                acc2[2 * i + 1] = __hfma2(e4m3x2_to_h2((uint16_t)(wv[i] >> 16)), wh, acc2[2 * i + 1]);
            }
        }
        __syncwarp();
    }
    denL += __shfl_xor_sync(0xffffffffu, denL, 4);
    denL += __shfl_xor_sync(0xffffffffu, denL, 8);
    denL += __shfl_xor_sync(0xffffffffu, denL, 16);
    float den = __shfl_sync(0xffffffffu, denL, h);
    float inv = 0.25f / (den + 1e-16f);

    float acc[PL];
    #pragma unroll
    for (int j = 0; j < NW * 2; j++) {
        float2 t = __half22float2(acc2[j]);
        acc[2 * j] = t.x;
        acc[2 * j + 1] = t.y;
    }
    #pragma unroll
    for (int j = 0; j < PL; j++) {
        float v = acc[j] * inv;
        v += __shfl_xor_sync(0xffffffffu, v, 8);
        v += __shfl_xor_sync(0xffffffffu, v, 16);
        acc[j] = v;
    }
    if (lane < 8) {
        int col = lane * PL;
        #pragma unroll
        for (int q = 0; q < PL / 4; q++) {
            float4 r = *(const float4*)(resid + (size_t)gw * C + col + q * 4);
            float4 o;
            o.x = acc[q * 4 + 0] + r.x;
            o.y = acc[q * 4 + 1] + r.y;
            o.z = acc[q * 4 + 2] + r.z;
            o.w = acc[q * 4 + 3] + r.w;
            *(float4*)(out + (size_t)gw * C + col + q * 4) = o;
        }
    }
}

// ---------------- graph boundaries ----------------
__global__ void k_gstart(const int* __restrict__ batch) {
    int i = blockIdx.x * blockDim.x + threadIdx.x;
    if (i >= NN) return;
    int b = batch[i];
    int bp = (i == 0) ? -1 : batch[i - 1];
    for (int g = bp + 1; g <= b; g++) d_gstart[g] = i;
    if (i == NN - 1)
        for (int g = b + 1; g <= NG; g++) d_gstart[g] = NN;
}

// ---------------- global mean pool ----------------
__global__ void k_pool() {
    int g = blockIdx.x;
    int start = d_gstart[g], end = d_gstart[g + 1];
    int c = threadIdx.x & 63;
    int stripe = threadIdx.x >> 6;
    float acc = 0.f;
    for (int r = start + stripe; r < end; r += 4) acc += d_h3[(size_t)r * 64 + c];
    __shared__ float sh[256];
    sh[threadIdx.x] = acc;
    __syncthreads();
    if (stripe == 0) {
        float v = sh[c] + sh[c + 64] + sh[c + 128] + sh[c + 192];
        float cnt = (float)(end - start);
        d_pooled[g * 64 + c] = v / fmaxf(cnt, 1.0f);
    }
}

// ---------------- classifier + log_softmax ----------------
__global__ void k_fc(const float* __restrict__ Wfc, const float* __restrict__ bfc,
                     float* __restrict__ out) {
    int g = threadIdx.x;
    if (g >= NG) return;
    float logits[10];
    #pragma unroll
    for (int o = 0; o < 10; o++) {
        float s = bfc[o];
        for (int c = 0; c < 64; c++) s += d_pooled[g * 64 + c] * Wfc[c * 10 + o];
        logits[o] = s;
    }
    float mx = logits[0];
    #pragma unroll
    for (int o = 1; o < 10; o++) mx = fmaxf(mx, logits[o]);
    float se = 0.f;
    #pragma unroll
    for (int o = 0; o < 10; o++) se += expf(logits[o] - mx);
    float lse = mx + logf(se);
    #pragma unroll
    for (int o = 0; o < 10; o++) out[g * 10 + o] = logits[o] - lse;
}

// ---------------- launch: dual-stream, half-split pipelined layers ----------------
extern "C" void kernel_launch(void* const* d_in, const int* in_sizes, int n_in,
                              void* d_out, int out_size) {
    const float* x    = (const float*)d_in[0];
    const int* edge   = (const int*)d_in[1];
    const int* batch  = (const int*)d_in[2];
    const float* Wm1  = (const float*)d_in[3];
    const float* bm1  = (const float*)d_in[4];
    const float* att1 = (const float*)d_in[5];
    const float* Ws1  = (const float*)d_in[6];
    const float* bs1  = (const float*)d_in[7];
    const float* Wm2  = (const float*)d_in[8];
    const float* bm2  = (const float*)d_in[9];
    const float* att2 = (const float*)d_in[10];
    const float* Wm3  = (const float*)d_in[11];
    const float* bm3  = (const float*)d_in[12];
    const float* att3 = (const float*)d_in[13];
    const float* Ws3  = (const float*)d_in[14];
    const float* bs3  = (const float*)d_in[15];
    const float* Wfc  = (const float*)d_in[16];
    const float* bfc  = (const float*)d_in[17];
    float* out = (float*)d_out;

    const int* srcp = edge;
    const int* dstp = edge + NE;

    float *S, *h1, *h2, *h3, *aNA, *aNB;
    uint8_t *M8A, *M8B;
    int* degp;
    cudaGetSymbolAddress((void**)&S, d_S);
    cudaGetSymbolAddress((void**)&h1, d_h1);
    cudaGetSymbolAddress((void**)&h2, d_h2);
    cudaGetSymbolAddress((void**)&h3, d_h3);
    cudaGetSymbolAddress((void**)&M8A, d_M8A);
    cudaGetSymbolAddress((void**)&M8B, d_M8B);
    cudaGetSymbolAddress((void**)&aNA, d_aNA);
    cudaGetSymbolAddress((void**)&aNB, d_aNB);
    cudaGetSymbolAddress((void**)&degp, d_deg);

    static cudaStream_t s2 = nullptr;
    static cudaEvent_t evFork, evG1, evC2, evA1h0, evG2h0, evG2h1, evC3, evA2h0, evG3h0, evGst;
    if (!s2) {
        cudaStreamCreateWithFlags(&s2, cudaStreamNonBlocking);
        cudaEventCreateWithFlags(&evFork, cudaEventDisableTiming);
        cudaEventCreateWithFlags(&evG1, cudaEventDisableTiming);
        cudaEventCreateWithFlags(&evC2, cudaEventDisableTiming);
        cudaEventCreateWithFlags(&evA1h0, cudaEventDisableTiming);
        cudaEventCreateWithFlags(&evG2h0, cudaEventDisableTiming);
        cudaEventCreateWithFlags(&evG2h1, cudaEventDisableTiming);
        cudaEventCreateWithFlags(&evC3, cudaEventDisableTiming);
        cudaEventCreateWithFlags(&evA2h0, cudaEventDisableTiming);
        cudaEventCreateWithFlags(&evG3h0, cudaEventDisableTiming);
        cudaEventCreateWithFlags(&evGst, cudaEventDisableTiming);
    }

    const int TB = 256;
    const int nodeBlocks = (NN + TB - 1) / TB;
    const int edgeBlocks = (NE + TB - 1) / TB;
    const int warpNodeBlocks = (NN * 32 + TB - 1) / TB;
    const int rowBlocks = (NN + 127) / 128;           // 391
    const int rbH0 = NS / 128;                        // 196
    const int rbH1 = (NN - NS + 127) / 128;           // 195
    const int aggH0 = (NS * 32 + TB - 1) / TB;        // 3136
    const int aggH1 = ((NN - NS) * 32 + TB - 1) / TB; // 3114
    cudaStream_t s0 = 0;

    cudaEventRecord(evFork, s0);
    cudaStreamWaitEvent(s2, evFork, 0);

    // ---- branch A (s0): CSR build ----
    cudaMemsetAsync(degp, 0, NN * sizeof(int), s0);
    k_degree<<<edgeBlocks, TB, 0, s0>>>(dstp);
    k_scan<<<1, 1024, 0, s0>>>();
    k_scatter<<<edgeBlocks, TB, 0, s0>>>(srcp, dstp);
    k_sortw<<<warpNodeBlocks, TB, 0, s0>>>();

    // ---- branch B (s2): gstart + layer-1 weights + GEMM1 (full), writes M8A/aNA/S ----
    k_gstart<<<nodeBlocks, TB, 0, s2>>>(batch);
    cudaEventRecord(evGst, s2);
    k_convW<<<(64 * 384 + TB - 1) / TB, TB, 0, s2>>>(Wm1, 64, 384, 0);
    k_convW<<<(64 * 96 + TB - 1) / TB, TB, 0, s2>>>(Ws1, 64, 96, 384);
    k_convAtt<<<1, 512, 0, s2>>>(Wm1, att1, bm1, 64, 96, 480);
    k_hgemm<64><<<dim3(rowBlocks, 4), TB, 0, s2>>>(x, bm1, bs1, M8A, S, aNA, 0, NN, 484, 384, 480, 384, 96);
    cudaEventRecord(evG1, s2);
    // layer-2 weights (overlap agg1)
    k_convW<<<(96 * 384 + TB - 1) / TB, TB, 0, s2>>>(Wm2, 96, 384, 0);
    k_convAtt<<<1, 512, 0, s2>>>(Wm2, att2, bm2, 96, 96, 384);
    cudaEventRecord(evC2, s2);

    // ---- agg1 h0 (s0): needs CSR (order) + GEMM1 ----
    cudaStreamWaitEvent(s0, evG1, 0);
    k_agg<96><<<aggH0, TB, 0, s0>>>(M8A, aNA, S, h1, 0, NS);
    cudaEventRecord(evA1h0, s0);
    // agg1 h1 (s0) concurrent with gemm2 h0 (s2)
    k_agg<96><<<aggH1, TB, 0, s0>>>(M8A, aNA, S, h1, NS, NN);

    // ---- gemm2 h0 on s2: needs agg1 h0 + conv2 (s2 order); writes M8B/aNB ----
    cudaStreamWaitEvent(s2, evA1h0, 0);
    k_hgemm<96><<<dim3(rbH0, 4), TB, 0, s2>>>(h1, bm2, bm2, M8B, S, aNB, 0, NN, 388, 384, 384, 384, 96);
    cudaEventRecord(evG2h0, s2);

    // ---- gemm2 h1 on s0 (after agg1 h1 in order; needs conv2) ----
    cudaStreamWaitEvent(s0, evC2, 0);
    k_hgemm<96><<<dim3(rbH1, 4), TB, 0, s0>>>(h1, bm2, bm2, M8B, S, aNB, NS, NN, 388, 384, 384, 384, 96);
    cudaEventRecord(evG2h1, s0);

    // ---- layer-3 weights on s2: need gemm2 fully done reading d_Wh ----
    cudaStreamWaitEvent(s2, evG2h1, 0);
    k_convW<<<(96 * 256 + TB - 1) / TB, TB, 0, s2>>>(Wm3, 96, 256, 0);
    k_convW<<<(96 * 64 + TB - 1) / TB, TB, 0, s2>>>(Ws3, 96, 64, 256);
    k_convAtt<<<1, 512, 0, s2>>>(Wm3, att3, bm3, 96, 64, 320);
    cudaEventRecord(evC3, s2);

    // ---- agg2 h0 (s0): needs gemm2 h0 (event) + h1 (order) ----
    cudaStreamWaitEvent(s0, evG2h0, 0);
    k_agg<96><<<aggH0, TB, 0, s0>>>(M8B, aNB, h1, h2, 0, NS);
    cudaEventRecord(evA2h0, s0);
    // agg2 h1 (s0) concurrent with gemm3 h0 (s2)
    k_agg<96><<<aggH1, TB, 0, s0>>>(M8B, aNB, h1, h2, NS, NN);

    // ---- gemm3 h0 on s2: needs agg2 h0 + conv3 (s2 order); writes M8A/aNA/S ----
    cudaStreamWaitEvent(s2, evA2h0, 0);
    k_hgemm<96><<<dim3(rbH0, 3), TB, 0, s2>>>(h2, bm3, bs3, M8A, S, aNA, 0, NN, 324, 256, 320, 256, 64);
    cudaEventRecord(evG3h0, s2);

    // ---- gemm3 h1 on s0 (after agg2 h1 in order; needs conv3) ----
    cudaStreamWaitEvent(s0, evC3, 0);
    k_hgemm<96><<<dim3(rbH1, 3), TB, 0, s0>>>(h2, bm3, bs3, M8A, S, aNA, NS, NN, 324, 256, 320, 256, 64);

    // ---- agg3 (s0): needs gemm3 h0 (event) + h1 (order) ----
    cudaStreamWaitEvent(s0, evG3h0, 0);
    k_agg<64><<<warpNodeBlocks, TB, 0, s0>>>(M8A, aNA, S, h3, 0, NN);

    // ---- pool + classifier ----
    cudaStreamWaitEvent(s0, evGst, 0);
    k_pool<<<NG, 256, 0, s0>>>();
    k_fc<<<1, 64, 0, s0>>>(Wfc, bfc, out);
}

// round 16
// speedup vs baseline: 1.4500x; 1.0146x over previous
#include <cuda_runtime.h>
#include <cuda_fp16.h>
#include <math.h>
#include <stdint.h>
#include <limits.h>

#define NN 50000
#define NE 400000
#define NG 64
#define NS 25088   // half split: 196 row-blocks of 128

// ---------------- static scratch (no allocations allowed) ----------------
__device__ __align__(16) uint8_t d_M8A[(size_t)NN * 384];
__device__ __align__(16) uint8_t d_M8B[(size_t)NN * 384];
__device__ __align__(16) float d_aNA[(size_t)NN * 4];
__device__ __align__(16) float d_aNB[(size_t)NN * 4];
__device__ float d_h1[(size_t)NN * 96];
__device__ float d_h2[(size_t)NN * 96];
__device__ float d_h3[(size_t)NN * 64];
__device__ float d_S[(size_t)NN * 96];
__device__ __align__(16) __half d_xH[(size_t)NN * 64];   // fp16 copies of GEMM inputs
__device__ __align__(16) __half d_h1H[(size_t)NN * 96];
__device__ __align__(16) __half d_h2H[(size_t)NN * 96];
__device__ int d_deg[NN];
__device__ int d_rowptr[NN + 1];
__device__ int d_cursor[NN];
__device__ int d_csrsrc[NE];
__device__ int d_gstart[NG + 1];
__device__ float d_pooled[NG * 64];
__device__ __align__(16) __half d_Wh[(size_t)512 * 96];
__device__ __align__(16) float d_batt[4];

// ---------------- fp8 helpers ----------------
__device__ __forceinline__ uint16_t f32x2_to_e4m3(float hi, float lo) {
    uint16_t o;
    asm("cvt.rn.satfinite.e4m3x2.f32 %0, %1, %2;" : "=h"(o) : "f"(hi), "f"(lo));
    return o;
}
__device__ __forceinline__ __half2 e4m3x2_to_h2(uint16_t v) {
    uint32_t r;
    asm("cvt.rn.f16x2.e4m3x2 %0, %1;" : "=r"(r) : "h"(v));
    return *(__half2*)&r;
}

// ---------------- CSR build ----------------
__global__ void k_degree(const int* __restrict__ dst) {
    int i = blockIdx.x * blockDim.x + threadIdx.x;
    if (i < NE) atomicAdd(&d_deg[dst[i]], 1);
}

__global__ void k_scan() {
    __shared__ int wsum[32];
    __shared__ int carrySh;
    int tid = threadIdx.x;
    int lane = tid & 31, w = tid >> 5;
    if (tid == 0) carrySh = 0;
    __syncthreads();
    for (int base = 0; base < NN; base += 1024) {
        int i = base + tid;
        int v = (i < NN) ? d_deg[i] : 0;
        int incl = v;
        #pragma unroll
        for (int off = 1; off < 32; off <<= 1) {
            int t = __shfl_up_sync(0xffffffffu, incl, off);
            if (lane >= off) incl += t;
        }
        if (lane == 31) wsum[w] = incl;
        __syncthreads();
        if (w == 0) {
            int s = wsum[lane];
            #pragma unroll
            for (int off = 1; off < 32; off <<= 1) {
                int t = __shfl_up_sync(0xffffffffu, s, off);
                if (lane >= off) s += t;
            }
            wsum[lane] = s;
        }
        __syncthreads();
        int woff = (w > 0) ? wsum[w - 1] : 0;
        int carry = carrySh;
        int total = wsum[31];
        __syncthreads();
        if (i < NN) {
            int ex = carry + woff + incl - v;
            d_rowptr[i] = ex;
            d_cursor[i] = ex;
        }
        if (tid == 0) carrySh = carry + total;
        __syncthreads();
    }
    if (tid == 0) d_rowptr[NN] = carrySh;
}

__global__ void k_scatter(const int* __restrict__ src, const int* __restrict__ dst) {
    int i = blockIdx.x * blockDim.x + threadIdx.x;
    if (i < NE) {
        int p = atomicAdd(&d_cursor[dst[i]], 1);
        d_csrsrc[p] = src[i];
    }
}

__global__ void k_sortw() {
    int gw = (blockIdx.x * blockDim.x + threadIdx.x) >> 5;
    int lane = threadIdx.x & 31;
    if (gw >= NN) return;
    int s = d_rowptr[gw], e = d_rowptr[gw + 1];
    int d = e - s;
    if (d <= 1) return;
    if (d <= 32) {
        int v = (lane < d) ? d_csrsrc[s + lane] : INT_MAX;
        #pragma unroll
        for (int k = 2; k <= 32; k <<= 1) {
            #pragma unroll
            for (int j = k >> 1; j > 0; j >>= 1) {
                int other = __shfl_xor_sync(0xffffffffu, v, j);
                bool dirUp = ((lane & k) == 0);
                bool lower = ((lane & j) == 0);
                int mn = min(v, other), mx = max(v, other);
                v = (dirUp == lower) ? mn : mx;
            }
        }
        if (lane < d) d_csrsrc[s + lane] = v;
    } else if (lane == 0) {
        for (int i = s + 1; i < e; i++) {
            int v = d_csrsrc[i];
            int j = i - 1;
            while (j >= s && d_csrsrc[j] > v) {
                d_csrsrc[j + 1] = d_csrsrc[j];
                j--;
            }
            d_csrsrc[j + 1] = v;
        }
    }
}

// ---------------- conversions ----------------
__global__ void k_convA16(const float* __restrict__ src, __half* __restrict__ dst, int n) {
    int i = blockIdx.x * blockDim.x + threadIdx.x;
    if (i * 2 < n) {
        float2 v = *(const float2*)(src + i * 2);
        *(__half2*)(dst + i * 2) = __floats2half2_rn(v.x, v.y);
    }
}

__global__ void k_convW(const float* __restrict__ W, int K, int Nout, int rowOff) {
    int idx = blockIdx.x * blockDim.x + threadIdx.x;
    if (idx >= K * Nout) return;
    int k = idx / Nout, n = idx - k * Nout;
    d_Wh[(size_t)(rowOff + n) * K + k] = __float2half(W[idx]);
}

__global__ void k_convAtt(const float* __restrict__ Wm, const float* __restrict__ att,
                          const float* __restrict__ bm, int K, int C, int rowA) {
    int t = threadIdx.x;
    int NC = 4 * C;
    if (t < K * 4) {
        int k = t >> 2, h = t & 3;
        float s = 0.f;
        for (int c = 0; c < C; c++) s += Wm[(size_t)k * NC + h * C + c] * att[h * C + c];
        d_Wh[(size_t)(rowA + h) * K + k] = __float2half(s);
    }
    if (t < 4) {
        float s = 0.f;
        for (int c = 0; c < C; c++) s += bm[t * C + c] * att[t * C + c];
        d_batt[t] = s;
    }
}

// ---------------- fp16 MMA GEMM (BK=32 loop, 16KB tiles, fp16 A input) ----------------
__device__ __forceinline__ uint32_t swz_off(int row, int c16) {
    return (uint32_t)((row << 6) + (((c16 ^ ((row >> 1) & 3)) & 3) << 4));
}

template <int K>
__global__ __launch_bounds__(256) void k_hgemm(
    const __half* __restrict__ Ah,
    const float* __restrict__ biasM, const float* __restrict__ biasS,
    uint8_t* __restrict__ M8, float* __restrict__ S, float* __restrict__ aN,
    int rowOff, int Mrows, int Nout, int NsplitM, int NsplitA, int strideM, int strideS)
{
    __shared__ __align__(16) char As[128 * 64];
    __shared__ __align__(16) char Bs[128 * 64];
    int tid = threadIdx.x;
    int wid = tid >> 5, lane = tid & 31;
    int r0 = rowOff + blockIdx.x * 128;
    int n0 = blockIdx.y * 128;
    int wm = (wid & 3) * 32;
    int wn = (wid >> 2) * 64;

    uint32_t AsAddr = (uint32_t)__cvta_generic_to_shared(As);
    uint32_t BsAddr = (uint32_t)__cvta_generic_to_shared(Bs);

    float acc[2][8][4];
    #pragma unroll
    for (int i = 0; i < 2; i++)
        #pragma unroll
        for (int j = 0; j < 8; j++)
            #pragma unroll
            for (int q = 0; q < 4; q++) acc[i][j][q] = 0.f;

    #pragma unroll
    for (int kb = 0; kb < K; kb += 32) {
        // ---- A tile: 128 rows x 32 fp16 loaded directly (512 16B chunks) ----
        #pragma unroll
        for (int it = 0; it < 2; it++) {
            int linear = tid + it * 256;
            int row = linear >> 2;
            int c16 = linear & 3;
            int gr = r0 + row;
            uint4 v = make_uint4(0u, 0u, 0u, 0u);
            if (gr < Mrows)
                v = *(const uint4*)(Ah + (size_t)gr * K + kb + c16 * 8);
            *(uint4*)(As + swz_off(row, c16)) = v;
        }
        // ---- B tile ----
        #pragma unroll
        for (int it = 0; it < 2; it++) {
            int linear = tid + it * 256;
            int row = linear >> 2;
            int c16 = linear & 3;
            int gn = n0 + row;
            uint4 v = make_uint4(0u, 0u, 0u, 0u);
            if (gn < Nout)
                v = *(const uint4*)(d_Wh + (size_t)gn * K + kb + c16 * 8);
            *(uint4*)(Bs + swz_off(row, c16)) = v;
        }
        __syncthreads();

        #pragma unroll
        for (int ks = 0; ks < 32; ks += 16) {
            uint32_t aF[2][4], bF[8][2];
            int q = lane >> 3;
            #pragma unroll
            for (int mt = 0; mt < 2; mt++) {
                int row = wm + mt * 16 + ((q & 1) << 3) + (lane & 7);
                int c16 = (ks >> 3) + (q >> 1);
                uint32_t addr = AsAddr + swz_off(row, c16);
                asm volatile("ldmatrix.sync.aligned.m8n8.x4.shared.b16 {%0,%1,%2,%3}, [%4];"
                    : "=r"(aF[mt][0]), "=r"(aF[mt][1]), "=r"(aF[mt][2]), "=r"(aF[mt][3])
                    : "r"(addr));
            }
            #pragma unroll
            for (int np = 0; np < 4; np++) {
                int row = wn + np * 16 + ((q >> 1) << 3) + (lane & 7);
                int c16 = (ks >> 3) + (q & 1);
                uint32_t addr = BsAddr + swz_off(row, c16);
                asm volatile("ldmatrix.sync.aligned.m8n8.x4.shared.b16 {%0,%1,%2,%3}, [%4];"
                    : "=r"(bF[2 * np][0]), "=r"(bF[2 * np][1]),
                      "=r"(bF[2 * np + 1][0]), "=r"(bF[2 * np + 1][1])
                    : "r"(addr));
            }
            #pragma unroll
            for (int mt = 0; mt < 2; mt++)
                #pragma unroll
                for (int nt = 0; nt < 8; nt++) {
                    asm volatile(
                        "mma.sync.aligned.m16n8k16.row.col.f32.f16.f16.f32 "
                        "{%0,%1,%2,%3}, {%4,%5,%6,%7}, {%8,%9}, {%0,%1,%2,%3};"
                        : "+f"(acc[mt][nt][0]), "+f"(acc[mt][nt][1]),
                          "+f"(acc[mt][nt][2]), "+f"(acc[mt][nt][3])
                        : "r"(aF[mt][0]), "r"(aF[mt][1]), "r"(aF[mt][2]), "r"(aF[mt][3]),
                          "r"(bF[nt][0]), "r"(bF[nt][1]));
                }
        }
        __syncthreads();
    }

    #pragma unroll
    for (int mt = 0; mt < 2; mt++) {
        int m = r0 + wm + mt * 16 + (lane >> 2);
        #pragma unroll
        for (int nt = 0; nt < 8; nt++) {
            int n = n0 + wn + nt * 8 + (lane & 3) * 2;
            if (n >= Nout) continue;
            if (n < NsplitM) {
                float2 bb = *(const float2*)(biasM + n);
                #pragma unroll
                for (int hf = 0; hf < 2; hf++) {
                    int mr = m + hf * 8;
                    if (mr < Mrows) {
                        uint16_t o = f32x2_to_e4m3(acc[mt][nt][2 * hf + 1] + bb.y,
                                                   acc[mt][nt][2 * hf] + bb.x);
                        *(uint16_t*)(M8 + (size_t)mr * strideM + n) = o;
                    }
                }
            } else if (n < NsplitA) {
                int nn = n - NsplitM;
                float2 bb = *(const float2*)(biasS + nn);
                #pragma unroll
                for (int hf = 0; hf < 2; hf++) {
                    int mr = m + hf * 8;
                    if (mr < Mrows) {
                        float2 o = make_float2(acc[mt][nt][2 * hf] + bb.x,
                                               acc[mt][nt][2 * hf + 1] + bb.y);
                        *(float2*)(S + (size_t)mr * strideS + nn) = o;
                    }
                }
            } else {
                int nn = n - NsplitA;
                float2 bb = *(const float2*)(d_batt + nn);
                #pragma unroll
                for (int hf = 0; hf < 2; hf++) {
                    int mr = m + hf * 8;
                    if (mr < Mrows) {
                        float vx = acc[mt][nt][2 * hf] + bb.x;
                        float vy = acc[mt][nt][2 * hf + 1] + bb.y;
                        vx = (vx > 0.f) ? vx : 0.2f * vx;
                        vy = (vy > 0.f) ? vy : 0.2f * vy;
                        *(float2*)(aN + (size_t)mr * 4 + nn) = make_float2(vx, vy);
                    }
                }
            }
        }
    }
}

// ---------------- aggregation: no max-pass, __expf; optional fp16 mirror output ----------------
template <int C>
__global__ __launch_bounds__(256) void k_agg(
    const uint8_t* __restrict__ M8, const float* __restrict__ aN,
    const float* __restrict__ resid, float* __restrict__ out,
    __half* __restrict__ outH,
    int nodeBeg, int nodeEnd)
{
    const int HC = 4 * C;
    const int PL = HC / 32;
    const int NW = PL / 4;
    __shared__ float wsh[8][8][4];
    __shared__ int ssh[8][8];
    int gw = nodeBeg + ((blockIdx.x * blockDim.x + threadIdx.x) >> 5);
    int lane = threadIdx.x & 31;
    int wId = threadIdx.x >> 5;
    if (gw >= nodeEnd) return;
    int start = d_rowptr[gw], end = d_rowptr[gw + 1];

    int h = lane >> 3;
    int hh = lane & 3;

    __half2 acc2[NW * 2];
    #pragma unroll
    for (int j = 0; j < NW * 2; j++) acc2[j] = __float2half2_rn(0.f);
    float denL = 0.f;
    int ei = lane >> 2;

    for (int base = start; base < end; base += 8) {
        int ne = end - base;
        if (ne > 8) ne = 8;
        if (ei < ne) {
            int sl = d_csrsrc[base + ei];
            float a = aN[(size_t)sl * 4 + hh];
            float wl = __expf(a);
            denL += wl;
            wsh[wId][ei][hh] = wl;
            if (hh == 0) ssh[wId][ei] = sl;
        }
        __syncwarp();
        for (int e = 0; e < ne; e++) {
            int s = ssh[wId][e];
            __half2 wh = __float2half2_rn(wsh[wId][e][h]);
            const uint32_t* rb = (const uint32_t*)(M8 + (size_t)s * HC + lane * PL);
            uint32_t wv[NW];
            #pragma unroll
            for (int i = 0; i < NW; i++) wv[i] = rb[i];
            #pragma unroll
            for (int i = 0; i < NW; i++) {
                acc2[2 * i] = __hfma2(e4m3x2_to_h2((uint16_t)wv[i]), wh, acc2[2 * i]);
                acc2[2 * i + 1] = __hfma2(e4m3x2_to_h2((uint16_t)(wv[i] >> 16)), wh, acc2[2 * i + 1]);
            }
        }
        __syncwarp();
    }
    denL += __shfl_xor_sync(0xffffffffu, denL, 4);
    denL += __shfl_xor_sync(0xffffffffu, denL, 8);
    denL += __shfl_xor_sync(0xffffffffu, denL, 16);
    float den = __shfl_sync(0xffffffffu, denL, h);
    float inv = 0.25f / (den + 1e-16f);

    float acc[PL];
    #pragma unroll
    for (int j = 0; j < NW * 2; j++) {
        float2 t = __half22float2(acc2[j]);
        acc[2 * j] = t.x;
        acc[2 * j + 1] = t.y;
    }
    #pragma unroll
    for (int j = 0; j < PL; j++) {
        float v = acc[j] * inv;
        v += __shfl_xor_sync(0xffffffffu, v, 8);
        v += __shfl_xor_sync(0xffffffffu, v, 16);
        acc[j] = v;
    }
    if (lane < 8) {
        int col = lane * PL;
        #pragma unroll
        for (int q = 0; q < PL / 4; q++) {
            float4 r = *(const float4*)(resid + (size_t)gw * C + col + q * 4);
            float4 o;
            o.x = acc[q * 4 + 0] + r.x;
            o.y = acc[q * 4 + 1] + r.y;
            o.z = acc[q * 4 + 2] + r.z;
            o.w = acc[q * 4 + 3] + r.w;
            *(float4*)(out + (size_t)gw * C + col + q * 4) = o;
            if (outH) {
                __half2 p0 = __floats2half2_rn(o.x, o.y);
                __half2 p1 = __floats2half2_rn(o.z, o.w);
                *(__half2*)(outH + (size_t)gw * C + col + q * 4) = p0;
                *(__half2*)(outH + (size_t)gw * C + col + q * 4 + 2) = p1;
            }
        }
    }
}

// ---------------- graph boundaries ----------------
__global__ void k_gstart(const int* __restrict__ batch) {
    int i = blockIdx.x * blockDim.x + threadIdx.x;
    if (i >= NN) return;
    int b = batch[i];
    int bp = (i == 0) ? -1 : batch[i - 1];
    for (int g = bp + 1; g <= b; g++) d_gstart[g] = i;
    if (i == NN - 1)
        for (int g = b + 1; g <= NG; g++) d_gstart[g] = NN;
}

// ---------------- global mean pool ----------------
__global__ void k_pool() {
    int g = blockIdx.x;
    int start = d_gstart[g], end = d_gstart[g + 1];
    int c = threadIdx.x & 63;
    int stripe = threadIdx.x >> 6;
    float acc = 0.f;
    for (int r = start + stripe; r < end; r += 4) acc += d_h3[(size_t)r * 64 + c];
    __shared__ float sh[256];
    sh[threadIdx.x] = acc;
    __syncthreads();
    if (stripe == 0) {
        float v = sh[c] + sh[c + 64] + sh[c + 128] + sh[c + 192];
        float cnt = (float)(end - start);
        d_pooled[g * 64 + c] = v / fmaxf(cnt, 1.0f);
    }
}

// ---------------- classifier + log_softmax ----------------
__global__ void k_fc(const float* __restrict__ Wfc, const float* __restrict__ bfc,
                     float* __restrict__ out) {
    int g = threadIdx.x;
    if (g >= NG) return;
    float logits[10];
    #pragma unroll
    for (int o = 0; o < 10; o++) {
        float s = bfc[o];
        for (int c = 0; c < 64; c++) s += d_pooled[g * 64 + c] * Wfc[c * 10 + o];
        logits[o] = s;
    }
    float mx = logits[0];
    #pragma unroll
    for (int o = 1; o < 10; o++) mx = fmaxf(mx, logits[o]);
    float se = 0.f;
    #pragma unroll
    for (int o = 0; o < 10; o++) se += expf(logits[o] - mx);
    float lse = mx + logf(se);
    #pragma unroll
    for (int o = 0; o < 10; o++) out[g * 10 + o] = logits[o] - lse;
}

// ---------------- launch: dual-stream, half-split pipelined layers ----------------
extern "C" void kernel_launch(void* const* d_in, const int* in_sizes, int n_in,
                              void* d_out, int out_size) {
    const float* x    = (const float*)d_in[0];
    const int* edge   = (const int*)d_in[1];
    const int* batch  = (const int*)d_in[2];
    const float* Wm1  = (const float*)d_in[3];
    const float* bm1  = (const float*)d_in[4];
    const float* att1 = (const float*)d_in[5];
    const float* Ws1  = (const float*)d_in[6];
    const float* bs1  = (const float*)d_in[7];
    const float* Wm2  = (const float*)d_in[8];
    const float* bm2  = (const float*)d_in[9];
    const float* att2 = (const float*)d_in[10];
    const float* Wm3  = (const float*)d_in[11];
    const float* bm3  = (const float*)d_in[12];
    const float* att3 = (const float*)d_in[13];
    const float* Ws3  = (const float*)d_in[14];
    const float* bs3  = (const float*)d_in[15];
    const float* Wfc  = (const float*)d_in[16];
    const float* bfc  = (const float*)d_in[17];
    float* out = (float*)d_out;

    const int* srcp = edge;
    const int* dstp = edge + NE;

    float *S, *h1, *h2, *h3, *aNA, *aNB;
    __half *xH, *h1H, *h2H;
    uint8_t *M8A, *M8B;
    int* degp;
    cudaGetSymbolAddress((void**)&S, d_S);
    cudaGetSymbolAddress((void**)&h1, d_h1);
    cudaGetSymbolAddress((void**)&h2, d_h2);
    cudaGetSymbolAddress((void**)&h3, d_h3);
    cudaGetSymbolAddress((void**)&xH, d_xH);
    cudaGetSymbolAddress((void**)&h1H, d_h1H);
    cudaGetSymbolAddress((void**)&h2H, d_h2H);
    cudaGetSymbolAddress((void**)&M8A, d_M8A);
    cudaGetSymbolAddress((void**)&M8B, d_M8B);
    cudaGetSymbolAddress((void**)&aNA, d_aNA);
    cudaGetSymbolAddress((void**)&aNB, d_aNB);
    cudaGetSymbolAddress((void**)&degp, d_deg);

    static cudaStream_t s2 = nullptr;
    static cudaEvent_t evFork, evG1, evC2, evA1h0, evG2h0, evG2h1, evC3, evA2h0, evG3h0, evGst;
    if (!s2) {
        cudaStreamCreateWithFlags(&s2, cudaStreamNonBlocking);
        cudaEventCreateWithFlags(&evFork, cudaEventDisableTiming);
        cudaEventCreateWithFlags(&evG1, cudaEventDisableTiming);
        cudaEventCreateWithFlags(&evC2, cudaEventDisableTiming);
        cudaEventCreateWithFlags(&evA1h0, cudaEventDisableTiming);
        cudaEventCreateWithFlags(&evG2h0, cudaEventDisableTiming);
        cudaEventCreateWithFlags(&evG2h1, cudaEventDisableTiming);
        cudaEventCreateWithFlags(&evC3, cudaEventDisableTiming);
        cudaEventCreateWithFlags(&evA2h0, cudaEventDisableTiming);
        cudaEventCreateWithFlags(&evG3h0, cudaEventDisableTiming);
        cudaEventCreateWithFlags(&evGst, cudaEventDisableTiming);
    }

    const int TB = 256;
    const int nodeBlocks = (NN + TB - 1) / TB;
    const int edgeBlocks = (NE + TB - 1) / TB;
    const int warpNodeBlocks = (NN * 32 + TB - 1) / TB;
    const int rowBlocks = (NN + 127) / 128;           // 391
    const int rbH0 = NS / 128;                        // 196
    const int rbH1 = (NN - NS + 127) / 128;           // 195
    const int aggH0 = (NS * 32 + TB - 1) / TB;        // 3136
    const int aggH1 = ((NN - NS) * 32 + TB - 1) / TB; // 3114
    cudaStream_t s0 = 0;

    cudaEventRecord(evFork, s0);
    cudaStreamWaitEvent(s2, evFork, 0);

    // ---- branch A (s0): CSR build ----
    cudaMemsetAsync(degp, 0, NN * sizeof(int), s0);
    k_degree<<<edgeBlocks, TB, 0, s0>>>(dstp);
    k_scan<<<1, 1024, 0, s0>>>();
    k_scatter<<<edgeBlocks, TB, 0, s0>>>(srcp, dstp);
    k_sortw<<<warpNodeBlocks, TB, 0, s0>>>();

    // ---- branch B (s2): gstart + xH + layer-1 weights + GEMM1, writes M8A/aNA/S ----
    k_gstart<<<nodeBlocks, TB, 0, s2>>>(batch);
    cudaEventRecord(evGst, s2);
    k_convA16<<<(NN * 64 / 2 + TB - 1) / TB, TB, 0, s2>>>(x, xH, NN * 64);
    k_convW<<<(64 * 384 + TB - 1) / TB, TB, 0, s2>>>(Wm1, 64, 384, 0);
    k_convW<<<(64 * 96 + TB - 1) / TB, TB, 0, s2>>>(Ws1, 64, 96, 384);
    k_convAtt<<<1, 512, 0, s2>>>(Wm1, att1, bm1, 64, 96, 480);
    k_hgemm<64><<<dim3(rowBlocks, 4), TB, 0, s2>>>(xH, bm1, bs1, M8A, S, aNA, 0, NN, 484, 384, 480, 384, 96);
    cudaEventRecord(evG1, s2);
    // layer-2 weights (overlap agg1)
    k_convW<<<(96 * 384 + TB - 1) / TB, TB, 0, s2>>>(Wm2, 96, 384, 0);
    k_convAtt<<<1, 512, 0, s2>>>(Wm2, att2, bm2, 96, 96, 384);
    cudaEventRecord(evC2, s2);

    // ---- agg1 h0 (s0): needs CSR (order) + GEMM1; writes h1 + h1H ----
    cudaStreamWaitEvent(s0, evG1, 0);
    k_agg<96><<<aggH0, TB, 0, s0>>>(M8A, aNA, S, h1, h1H, 0, NS);
    cudaEventRecord(evA1h0, s0);
    k_agg<96><<<aggH1, TB, 0, s0>>>(M8A, aNA, S, h1, h1H, NS, NN);

    // ---- gemm2 h0 on s2: needs agg1 h0 + conv2 (s2 order); writes M8B/aNB ----
    cudaStreamWaitEvent(s2, evA1h0, 0);
    k_hgemm<96><<<dim3(rbH0, 4), TB, 0, s2>>>(h1H, bm2, bm2, M8B, S, aNB, 0, NN, 388, 384, 384, 384, 96);
    cudaEventRecord(evG2h0, s2);

    // ---- gemm2 h1 on s0 (after agg1 h1 in order; needs conv2) ----
    cudaStreamWaitEvent(s0, evC2, 0);
    k_hgemm<96><<<dim3(rbH1, 4), TB, 0, s0>>>(h1H, bm2, bm2, M8B, S, aNB, NS, NN, 388, 384, 384, 384, 96);
    cudaEventRecord(evG2h1, s0);

    // ---- layer-3 weights on s2: need gemm2 fully done reading d_Wh ----
    cudaStreamWaitEvent(s2, evG2h1, 0);
    k_convW<<<(96 * 256 + TB - 1) / TB, TB, 0, s2>>>(Wm3, 96, 256, 0);
    k_convW<<<(96 * 64 + TB - 1) / TB, TB, 0, s2>>>(Ws3, 96, 64, 256);
    k_convAtt<<<1, 512, 0, s2>>>(Wm3, att3, bm3, 96, 64, 320);
    cudaEventRecord(evC3, s2);

    // ---- agg2 h0 (s0): writes h2 + h2H ----
    cudaStreamWaitEvent(s0, evG2h0, 0);
    k_agg<96><<<aggH0, TB, 0, s0>>>(M8B, aNB, h1, h2, h2H, 0, NS);
    cudaEventRecord(evA2h0, s0);
    k_agg<96><<<aggH1, TB, 0, s0>>>(M8B, aNB, h1, h2, h2H, NS, NN);

    // ---- gemm3 h0 on s2: needs agg2 h0 + conv3 (s2 order); writes M8A/aNA/S ----
    cudaStreamWaitEvent(s2, evA2h0, 0);
    k_hgemm<96><<<dim3(rbH0, 3), TB, 0, s2>>>(h2H, bm3, bs3, M8A, S, aNA, 0, NN, 324, 256, 320, 256, 64);
    cudaEventRecord(evG3h0, s2);

    // ---- gemm3 h1 on s0 (after agg2 h1 in order; needs conv3) ----
    cudaStreamWaitEvent(s0, evC3, 0);
    k_hgemm<96><<<dim3(rbH1, 3), TB, 0, s0>>>(h2H, bm3, bs3, M8A, S, aNA, NS, NN, 324, 256, 320, 256, 64);

    // ---- agg3 (s0): fp32 only ----
    cudaStreamWaitEvent(s0, evG3h0, 0);
    k_agg<64><<<warpNodeBlocks, TB, 0, s0>>>(M8A, aNA, S, h3, ((__half*)0), 0, NN);

    // ---- pool + classifier ----
    cudaStreamWaitEvent(s0, evGst, 0);
    k_pool<<<NG, 256, 0, s0>>>();
    k_fc<<<1, 64, 0, s0>>>(Wfc, bfc, out);
}

// round 17
// speedup vs baseline: 1.4610x; 1.0075x over previous
#include <cuda_runtime.h>
#include <cuda_fp16.h>
#include <math.h>
#include <stdint.h>
#include <limits.h>

#define NN 50000
#define NE 400000
#define NG 64
#define NS 25088   // half split: 196 row-blocks of 128

// ---------------- static scratch (no allocations allowed) ----------------
__device__ __align__(16) uint8_t d_M8A[(size_t)NN * 384];
__device__ __align__(16) uint8_t d_M8B[(size_t)NN * 384];
__device__ __align__(16) float d_aNA[(size_t)NN * 4];
__device__ __align__(16) float d_aNB[(size_t)NN * 4];
__device__ float d_h1[(size_t)NN * 96];
__device__ float d_h2[(size_t)NN * 96];
__device__ float d_h3[(size_t)NN * 64];
__device__ float d_S[(size_t)NN * 96];
__device__ __align__(16) __half d_xH[(size_t)NN * 64];
__device__ __align__(16) __half d_h1H[(size_t)NN * 96];
__device__ __align__(16) __half d_h2H[(size_t)NN * 96];
__device__ int d_deg[NN];
__device__ int d_rowptr[NN + 1];
__device__ int d_cursor[NN];
__device__ int d_csrsrc[NE];
__device__ int d_gstart[NG + 1];
__device__ float d_pooled[NG * 64];
__device__ __align__(16) __half d_Wh[(size_t)512 * 96];
__device__ __align__(16) float d_batt[4];

// ---------------- fp8 helpers ----------------
__device__ __forceinline__ uint16_t f32x2_to_e4m3(float hi, float lo) {
    uint16_t o;
    asm("cvt.rn.satfinite.e4m3x2.f32 %0, %1, %2;" : "=h"(o) : "f"(hi), "f"(lo));
    return o;
}
__device__ __forceinline__ __half2 e4m3x2_to_h2(uint16_t v) {
    uint32_t r;
    asm("cvt.rn.f16x2.e4m3x2 %0, %1;" : "=r"(r) : "h"(v));
    return *(__half2*)&r;
}

// ---------------- CSR build ----------------
__global__ void k_degree(const int* __restrict__ dst) {
    int i = blockIdx.x * blockDim.x + threadIdx.x;
    if (i < NE) atomicAdd(&d_deg[dst[i]], 1);
}

__global__ void k_scan() {
    __shared__ int wsum[32];
    __shared__ int carrySh;
    int tid = threadIdx.x;
    int lane = tid & 31, w = tid >> 5;
    if (tid == 0) carrySh = 0;
    __syncthreads();
    for (int base = 0; base < NN; base += 1024) {
        int i = base + tid;
        int v = (i < NN) ? d_deg[i] : 0;
        int incl = v;
        #pragma unroll
        for (int off = 1; off < 32; off <<= 1) {
            int t = __shfl_up_sync(0xffffffffu, incl, off);
            if (lane >= off) incl += t;
        }
        if (lane == 31) wsum[w] = incl;
        __syncthreads();
        if (w == 0) {
            int s = wsum[lane];
            #pragma unroll
            for (int off = 1; off < 32; off <<= 1) {
                int t = __shfl_up_sync(0xffffffffu, s, off);
                if (lane >= off) s += t;
            }
            wsum[lane] = s;
        }
        __syncthreads();
        int woff = (w > 0) ? wsum[w - 1] : 0;
        int carry = carrySh;
        int total = wsum[31];
        __syncthreads();
        if (i < NN) {
            int ex = carry + woff + incl - v;
            d_rowptr[i] = ex;
            d_cursor[i] = ex;
        }
        if (tid == 0) carrySh = carry + total;
        __syncthreads();
    }
    if (tid == 0) d_rowptr[NN] = carrySh;
}

__global__ void k_scatter(const int* __restrict__ src, const int* __restrict__ dst) {
    int i = blockIdx.x * blockDim.x + threadIdx.x;
    if (i < NE) {
        int p = atomicAdd(&d_cursor[dst[i]], 1);
        d_csrsrc[p] = src[i];
    }
}

__global__ void k_sortw() {
    int gw = (blockIdx.x * blockDim.x + threadIdx.x) >> 5;
    int lane = threadIdx.x & 31;
    if (gw >= NN) return;
    int s = d_rowptr[gw], e = d_rowptr[gw + 1];
    int d = e - s;
    if (d <= 1) return;
    if (d <= 32) {
        int v = (lane < d) ? d_csrsrc[s + lane] : INT_MAX;
        #pragma unroll
        for (int k = 2; k <= 32; k <<= 1) {
            #pragma unroll
            for (int j = k >> 1; j > 0; j >>= 1) {
                int other = __shfl_xor_sync(0xffffffffu, v, j);
                bool dirUp = ((lane & k) == 0);
                bool lower = ((lane & j) == 0);
                int mn = min(v, other), mx = max(v, other);
                v = (dirUp == lower) ? mn : mx;
            }
        }
        if (lane < d) d_csrsrc[s + lane] = v;
    } else if (lane == 0) {
        for (int i = s + 1; i < e; i++) {
            int v = d_csrsrc[i];
            int j = i - 1;
            while (j >= s && d_csrsrc[j] > v) {
                d_csrsrc[j + 1] = d_csrsrc[j];
                j--;
            }
            d_csrsrc[j + 1] = v;
        }
    }
}

// ---------------- conversions ----------------
__global__ void k_convA16(const float* __restrict__ src, __half* __restrict__ dst, int n) {
    int i = blockIdx.x * blockDim.x + threadIdx.x;
    if (i * 2 < n) {
        float2 v = *(const float2*)(src + i * 2);
        *(__half2*)(dst + i * 2) = __floats2half2_rn(v.x, v.y);
    }
}

__global__ void k_convW(const float* __restrict__ W, int K, int Nout, int rowOff) {
    int idx = blockIdx.x * blockDim.x + threadIdx.x;
    if (idx >= K * Nout) return;
    int k = idx / Nout, n = idx - k * Nout;
    d_Wh[(size_t)(rowOff + n) * K + k] = __float2half(W[idx]);
}

__global__ void k_convAtt(const float* __restrict__ Wm, const float* __restrict__ att,
                          const float* __restrict__ bm, int K, int C, int rowA) {
    int t = threadIdx.x;
    int NC = 4 * C;
    if (t < K * 4) {
        int k = t >> 2, h = t & 3;
        float s = 0.f;
        for (int c = 0; c < C; c++) s += Wm[(size_t)k * NC + h * C + c] * att[h * C + c];
        d_Wh[(size_t)(rowA + h) * K + k] = __float2half(s);
    }
    if (t < 4) {
        float s = 0.f;
        for (int c = 0; c < C; c++) s += bm[t * C + c] * att[t * C + c];
        d_batt[t] = s;
    }
}

// ---------------- alpha GEMV: aN[n,h] = leaky(sum_k A[n,k]*Wh[rowA+h,k] + batt[h]) ----------------
// warp per node, K=96
__global__ __launch_bounds__(256) void k_alphaGemv(
    const float* __restrict__ A, float* __restrict__ aN, int rowA)
{
    int gw = (blockIdx.x * blockDim.x + threadIdx.x) >> 5;
    int lane = threadIdx.x & 31;
    if (gw >= NN) return;
    float a0 = A[(size_t)gw * 96 + lane];
    float a1 = A[(size_t)gw * 96 + 32 + lane];
    float a2 = A[(size_t)gw * 96 + 64 + lane];
    float s[4];
    #pragma unroll
    for (int h = 0; h < 4; h++) {
        const __half* w = d_Wh + (size_t)(rowA + h) * 96;
        float t = a0 * __half2float(w[lane])
                + a1 * __half2float(w[32 + lane])
                + a2 * __half2float(w[64 + lane]);
        #pragma unroll
        for (int off = 16; off > 0; off >>= 1)
            t += __shfl_xor_sync(0xffffffffu, t, off);
        s[h] = t;
    }
    if (lane < 4) {
        float v = s[lane] + d_batt[lane];
        v = (v > 0.f) ? v : 0.2f * v;
        aN[(size_t)gw * 4 + lane] = v;
    }
}

// ---------------- fp16 MMA GEMM (BK=32 loop, 16KB tiles, fp16 A input) ----------------
__device__ __forceinline__ uint32_t swz_off(int row, int c16) {
    return (uint32_t)((row << 6) + (((c16 ^ ((row >> 1) & 3)) & 3) << 4));
}

template <int K>
__global__ __launch_bounds__(256) void k_hgemm(
    const __half* __restrict__ Ah,
    const float* __restrict__ biasM, const float* __restrict__ biasS,
    uint8_t* __restrict__ M8, float* __restrict__ S, float* __restrict__ aN,
    int rowOff, int Mrows, int Nout, int NsplitM, int NsplitA, int strideM, int strideS)
{
    __shared__ __align__(16) char As[128 * 64];
    __shared__ __align__(16) char Bs[128 * 64];
    int tid = threadIdx.x;
    int wid = tid >> 5, lane = tid & 31;
    int r0 = rowOff + blockIdx.x * 128;
    int n0 = blockIdx.y * 128;
    int wm = (wid & 3) * 32;
    int wn = (wid >> 2) * 64;

    uint32_t AsAddr = (uint32_t)__cvta_generic_to_shared(As);
    uint32_t BsAddr = (uint32_t)__cvta_generic_to_shared(Bs);

    float acc[2][8][4];
    #pragma unroll
    for (int i = 0; i < 2; i++)
        #pragma unroll
        for (int j = 0; j < 8; j++)
            #pragma unroll
            for (int q = 0; q < 4; q++) acc[i][j][q] = 0.f;

    #pragma unroll
    for (int kb = 0; kb < K; kb += 32) {
        #pragma unroll
        for (int it = 0; it < 2; it++) {
            int linear = tid + it * 256;
            int row = linear >> 2;
            int c16 = linear & 3;
            int gr = r0 + row;
            uint4 v = make_uint4(0u, 0u, 0u, 0u);
            if (gr < Mrows)
                v = *(const uint4*)(Ah + (size_t)gr * K + kb + c16 * 8);
            *(uint4*)(As + swz_off(row, c16)) = v;
        }
        #pragma unroll
        for (int it = 0; it < 2; it++) {
            int linear = tid + it * 256;
            int row = linear >> 2;
            int c16 = linear & 3;
            int gn = n0 + row;
            uint4 v = make_uint4(0u, 0u, 0u, 0u);
            if (gn < Nout)
                v = *(const uint4*)(d_Wh + (size_t)gn * K + kb + c16 * 8);
            *(uint4*)(Bs + swz_off(row, c16)) = v;
        }
        __syncthreads();

        #pragma unroll
        for (int ks = 0; ks < 32; ks += 16) {
            uint32_t aF[2][4], bF[8][2];
            int q = lane >> 3;
            #pragma unroll
            for (int mt = 0; mt < 2; mt++) {
                int row = wm + mt * 16 + ((q & 1) << 3) + (lane & 7);
                int c16 = (ks >> 3) + (q >> 1);
                uint32_t addr = AsAddr + swz_off(row, c16);
                asm volatile("ldmatrix.sync.aligned.m8n8.x4.shared.b16 {%0,%1,%2,%3}, [%4];"
                    : "=r"(aF[mt][0]), "=r"(aF[mt][1]), "=r"(aF[mt][2]), "=r"(aF[mt][3])
                    : "r"(addr));
            }
            #pragma unroll
            for (int np = 0; np < 4; np++) {
                int row = wn + np * 16 + ((q >> 1) << 3) + (lane & 7);
                int c16 = (ks >> 3) + (q & 1);
                uint32_t addr = BsAddr + swz_off(row, c16);
                asm volatile("ldmatrix.sync.aligned.m8n8.x4.shared.b16 {%0,%1,%2,%3}, [%4];"
                    : "=r"(bF[2 * np][0]), "=r"(bF[2 * np][1]),
                      "=r"(bF[2 * np + 1][0]), "=r"(bF[2 * np + 1][1])
                    : "r"(addr));
            }
            #pragma unroll
            for (int mt = 0; mt < 2; mt++)
                #pragma unroll
                for (int nt = 0; nt < 8; nt++) {
                    asm volatile(
                        "mma.sync.aligned.m16n8k16.row.col.f32.f16.f16.f32 "
                        "{%0,%1,%2,%3}, {%4,%5,%6,%7}, {%8,%9}, {%0,%1,%2,%3};"
                        : "+f"(acc[mt][nt][0]), "+f"(acc[mt][nt][1]),
                          "+f"(acc[mt][nt][2]), "+f"(acc[mt][nt][3])
                        : "r"(aF[mt][0]), "r"(aF[mt][1]), "r"(aF[mt][2]), "r"(aF[mt][3]),
                          "r"(bF[nt][0]), "r"(bF[nt][1]));
                }
        }
        __syncthreads();
    }

    #pragma unroll
    for (int mt = 0; mt < 2; mt++) {
        int m = r0 + wm + mt * 16 + (lane >> 2);
        #pragma unroll
        for (int nt = 0; nt < 8; nt++) {
            int n = n0 + wn + nt * 8 + (lane & 3) * 2;
            if (n >= Nout) continue;
            if (n < NsplitM) {
                float2 bb = *(const float2*)(biasM + n);
                #pragma unroll
                for (int hf = 0; hf < 2; hf++) {
                    int mr = m + hf * 8;
                    if (mr < Mrows) {
                        uint16_t o = f32x2_to_e4m3(acc[mt][nt][2 * hf + 1] + bb.y,
                                                   acc[mt][nt][2 * hf] + bb.x);
                        *(uint16_t*)(M8 + (size_t)mr * strideM + n) = o;
                    }
                }
            } else if (n < NsplitA) {
                int nn = n - NsplitM;
                float2 bb = *(const float2*)(biasS + nn);
                #pragma unroll
                for (int hf = 0; hf < 2; hf++) {
                    int mr = m + hf * 8;
                    if (mr < Mrows) {
                        float2 o = make_float2(acc[mt][nt][2 * hf] + bb.x,
                                               acc[mt][nt][2 * hf + 1] + bb.y);
                        *(float2*)(S + (size_t)mr * strideS + nn) = o;
                    }
                }
            } else {
                int nn = n - NsplitA;
                float2 bb = *(const float2*)(d_batt + nn);
                #pragma unroll
                for (int hf = 0; hf < 2; hf++) {
                    int mr = m + hf * 8;
                    if (mr < Mrows) {
                        float vx = acc[mt][nt][2 * hf] + bb.x;
                        float vy = acc[mt][nt][2 * hf + 1] + bb.y;
                        vx = (vx > 0.f) ? vx : 0.2f * vx;
                        vy = (vy > 0.f) ? vy : 0.2f * vy;
                        *(float2*)(aN + (size_t)mr * 4 + nn) = make_float2(vx, vy);
                    }
                }
            }
        }
    }
}

// ---------------- aggregation: no max-pass, __expf; optional fp16 mirror output ----------------
template <int C>
__global__ __launch_bounds__(256) void k_agg(
    const uint8_t* __restrict__ M8, const float* __restrict__ aN,
    const float* __restrict__ resid, float* __restrict__ out,
    __half* __restrict__ outH,
    int nodeBeg, int nodeEnd)
{
    const int HC = 4 * C;
    const int PL = HC / 32;
    const int NW = PL / 4;
    __shared__ float wsh[8][8][4];
    __shared__ int ssh[8][8];
    int gw = nodeBeg + ((blockIdx.x * blockDim.x + threadIdx.x) >> 5);
    int lane = threadIdx.x & 31;
    int wId = threadIdx.x >> 5;
    if (gw >= nodeEnd) return;
    int start = d_rowptr[gw], end = d_rowptr[gw + 1];

    int h = lane >> 3;
    int hh = lane & 3;

    __half2 acc2[NW * 2];
    #pragma unroll
    for (int j = 0; j < NW * 2; j++) acc2[j] = __float2half2_rn(0.f);
    float denL = 0.f;
    int ei = lane >> 2;

    for (int base = start; base < end; base += 8) {
        int ne = end - base;
        if (ne > 8) ne = 8;
        if (ei < ne) {
            int sl = d_csrsrc[base + ei];
            float a = aN[(size_t)sl * 4 + hh];
            float wl = __expf(a);
            denL += wl;
            wsh[wId][ei][hh] = wl;
            if (hh == 0) ssh[wId][ei] = sl;
        }
        __syncwarp();
        for (int e = 0; e < ne; e++) {
            int s = ssh[wId][e];
            __half2 wh = __float2half2_rn(wsh[wId][e][h]);
            const uint32_t* rb = (const uint32_t*)(M8 + (size_t)s * HC + lane * PL);
            uint32_t wv[NW];
            #pragma unroll
            for (int i = 0; i < NW; i++) wv[i] = rb[i];
            #pragma unroll
            for (int i = 0; i < NW; i++) {
                acc2[2 * i] = __hfma2(e4m3x2_to_h2((uint16_t)wv[i]), wh, acc2[2 * i]);
                acc2[2 * i + 1] = __hfma2(e4m3x2_to_h2((uint16_t)(wv[i] >> 16)), wh, acc2[2 * i + 1]);
            }
        }
        __syncwarp();
    }
    denL += __shfl_xor_sync(0xffffffffu, denL, 4);
    denL += __shfl_xor_sync(0xffffffffu, denL, 8);
    denL += __shfl_xor_sync(0xffffffffu, denL, 16);
    float den = __shfl_sync(0xffffffffu, denL, h);
    float inv = 0.25f / (den + 1e-16f);

    float acc[PL];
    #pragma unroll
    for (int j = 0; j < NW * 2; j++) {
        float2 t = __half22float2(acc2[j]);
        acc[2 * j] = t.x;
        acc[2 * j + 1] = t.y;
    }
    #pragma unroll
    for (int j = 0; j < PL; j++) {
        float v = acc[j] * inv;
        v += __shfl_xor_sync(0xffffffffu, v, 8);
        v += __shfl_xor_sync(0xffffffffu, v, 16);
        acc[j] = v;
    }
    if (lane < 8) {
        int col = lane * PL;
        #pragma unroll
        for (int q = 0; q < PL / 4; q++) {
            float4 r = *(const float4*)(resid + (size_t)gw * C + col + q * 4);
            float4 o;
            o.x = acc[q * 4 + 0] + r.x;
            o.y = acc[q * 4 + 1] + r.y;
            o.z = acc[q * 4 + 2] + r.z;
            o.w = acc[q * 4 + 3] + r.w;
            *(float4*)(out + (size_t)gw * C + col + q * 4) = o;
            if (outH) {
                __half2 p0 = __floats2half2_rn(o.x, o.y);
                __half2 p1 = __floats2half2_rn(o.z, o.w);
                *(__half2*)(outH + (size_t)gw * C + col + q * 4) = p0;
                *(__half2*)(outH + (size_t)gw * C + col + q * 4 + 2) = p1;
            }
        }
    }
}

// ---------------- graph boundaries ----------------
__global__ void k_gstart(const int* __restrict__ batch) {
    int i = blockIdx.x * blockDim.x + threadIdx.x;
    if (i >= NN) return;
    int b = batch[i];
    int bp = (i == 0) ? -1 : batch[i - 1];
    for (int g = bp + 1; g <= b; g++) d_gstart[g] = i;
    if (i == NN - 1)
        for (int g = b + 1; g <= NG; g++) d_gstart[g] = NN;
}

// ---------------- global mean pool ----------------
__global__ void k_pool() {
    int g = blockIdx.x;
    int start = d_gstart[g], end = d_gstart[g + 1];
    int c = threadIdx.x & 63;
    int stripe = threadIdx.x >> 6;
    float acc = 0.f;
    for (int r = start + stripe; r < end; r += 4) acc += d_h3[(size_t)r * 64 + c];
    __shared__ float sh[256];
    sh[threadIdx.x] = acc;
    __syncthreads();
    if (stripe == 0) {
        float v = sh[c] + sh[c + 64] + sh[c + 128] + sh[c + 192];
        float cnt = (float)(end - start);
        d_pooled[g * 64 + c] = v / fmaxf(cnt, 1.0f);
    }
}

// ---------------- classifier + log_softmax ----------------
__global__ void k_fc(const float* __restrict__ Wfc, const float* __restrict__ bfc,
                     float* __restrict__ out) {
    int g = threadIdx.x;
    if (g >= NG) return;
    float logits[10];
    #pragma unroll
    for (int o = 0; o < 10; o++) {
        float s = bfc[o];
        for (int c = 0; c < 64; c++) s += d_pooled[g * 64 + c] * Wfc[c * 10 + o];
        logits[o] = s;
    }
    float mx = logits[0];
    #pragma unroll
    for (int o = 1; o < 10; o++) mx = fmaxf(mx, logits[o]);
    float se = 0.f;
    #pragma unroll
    for (int o = 0; o < 10; o++) se += expf(logits[o] - mx);
    float lse = mx + logf(se);
    #pragma unroll
    for (int o = 0; o < 10; o++) out[g * 10 + o] = logits[o] - lse;
}

// ---------------- launch: tri-stream pipelined ----------------
extern "C" void kernel_launch(void* const* d_in, const int* in_sizes, int n_in,
                              void* d_out, int out_size) {
    const float* x    = (const float*)d_in[0];
    const int* edge   = (const int*)d_in[1];
    const int* batch  = (const int*)d_in[2];
    const float* Wm1  = (const float*)d_in[3];
    const float* bm1  = (const float*)d_in[4];
    const float* att1 = (const float*)d_in[5];
    const float* Ws1  = (const float*)d_in[6];
    const float* bs1  = (const float*)d_in[7];
    const float* Wm2  = (const float*)d_in[8];
    const float* bm2  = (const float*)d_in[9];
    const float* att2 = (const float*)d_in[10];
    const float* Wm3  = (const float*)d_in[11];
    const float* bm3  = (const float*)d_in[12];
    const float* att3 = (const float*)d_in[13];
    const float* Ws3  = (const float*)d_in[14];
    const float* bs3  = (const float*)d_in[15];
    const float* Wfc  = (const float*)d_in[16];
    const float* bfc  = (const float*)d_in[17];
    float* out = (float*)d_out;

    const int* srcp = edge;
    const int* dstp = edge + NE;

    float *S, *h1, *h2, *h3, *aNA, *aNB;
    __half *xH, *h1H, *h2H;
    uint8_t *M8A, *M8B;
    int* degp;
    cudaGetSymbolAddress((void**)&S, d_S);
    cudaGetSymbolAddress((void**)&h1, d_h1);
    cudaGetSymbolAddress((void**)&h2, d_h2);
    cudaGetSymbolAddress((void**)&h3, d_h3);
    cudaGetSymbolAddress((void**)&xH, d_xH);
    cudaGetSymbolAddress((void**)&h1H, d_h1H);
    cudaGetSymbolAddress((void**)&h2H, d_h2H);
    cudaGetSymbolAddress((void**)&M8A, d_M8A);
    cudaGetSymbolAddress((void**)&M8B, d_M8B);
    cudaGetSymbolAddress((void**)&aNA, d_aNA);
    cudaGetSymbolAddress((void**)&aNB, d_aNB);
    cudaGetSymbolAddress((void**)&degp, d_deg);

    static cudaStream_t s2 = nullptr, s3 = nullptr;
    static cudaEvent_t evFork, evG1, evC2, evA1h0, evA1h1, evG2h0, evG2h1, evC3,
                       evA2h0, evG3h0, evGst, evXH;
    if (!s2) {
        cudaStreamCreateWithFlags(&s2, cudaStreamNonBlocking);
        cudaStreamCreateWithFlags(&s3, cudaStreamNonBlocking);
        cudaEventCreateWithFlags(&evFork, cudaEventDisableTiming);
        cudaEventCreateWithFlags(&evG1, cudaEventDisableTiming);
        cudaEventCreateWithFlags(&evC2, cudaEventDisableTiming);
        cudaEventCreateWithFlags(&evA1h0, cudaEventDisableTiming);
        cudaEventCreateWithFlags(&evA1h1, cudaEventDisableTiming);
        cudaEventCreateWithFlags(&evG2h0, cudaEventDisableTiming);
        cudaEventCreateWithFlags(&evG2h1, cudaEventDisableTiming);
        cudaEventCreateWithFlags(&evC3, cudaEventDisableTiming);
        cudaEventCreateWithFlags(&evA2h0, cudaEventDisableTiming);
        cudaEventCreateWithFlags(&evG3h0, cudaEventDisableTiming);
        cudaEventCreateWithFlags(&evGst, cudaEventDisableTiming);
        cudaEventCreateWithFlags(&evXH, cudaEventDisableTiming);
    }

    const int TB = 256;
    const int nodeBlocks = (NN + TB - 1) / TB;
    const int edgeBlocks = (NE + TB - 1) / TB;
    const int warpNodeBlocks = (NN * 32 + TB - 1) / TB;
    const int rowBlocks = (NN + 127) / 128;           // 391
    const int rbH0 = NS / 128;                        // 196
    const int rbH1 = (NN - NS + 127) / 128;           // 195
    const int aggH0 = (NS * 32 + TB - 1) / TB;        // 3136
    const int aggH1 = ((NN - NS) * 32 + TB - 1) / TB; // 3114
    cudaStream_t s0 = 0;

    cudaEventRecord(evFork, s0);
    cudaStreamWaitEvent(s2, evFork, 0);
    cudaStreamWaitEvent(s3, evFork, 0);

    // ---- branch A (s0): CSR build ----
    cudaMemsetAsync(degp, 0, NN * sizeof(int), s0);
    k_degree<<<edgeBlocks, TB, 0, s0>>>(dstp);
    k_scan<<<1, 1024, 0, s0>>>();
    k_scatter<<<edgeBlocks, TB, 0, s0>>>(srcp, dstp);
    k_sortw<<<warpNodeBlocks, TB, 0, s0>>>();

    // ---- branch C (s3): xH conversion + gstart ----
    k_convA16<<<(NN * 64 / 2 + TB - 1) / TB, TB, 0, s3>>>(x, xH, NN * 64);
    cudaEventRecord(evXH, s3);
    k_gstart<<<nodeBlocks, TB, 0, s3>>>(batch);
    cudaEventRecord(evGst, s3);

    // ---- branch B (s2): layer-1 weights + GEMM1, writes M8A/aNA/S ----
    k_convW<<<(64 * 384 + TB - 1) / TB, TB, 0, s2>>>(Wm1, 64, 384, 0);
    k_convW<<<(64 * 96 + TB - 1) / TB, TB, 0, s2>>>(Ws1, 64, 96, 384);
    k_convAtt<<<1, 512, 0, s2>>>(Wm1, att1, bm1, 64, 96, 480);
    cudaStreamWaitEvent(s2, evXH, 0);
    k_hgemm<64><<<dim3(rowBlocks, 4), TB, 0, s2>>>(xH, bm1, bs1, M8A, S, aNA, 0, NN, 484, 384, 480, 384, 96);
    cudaEventRecord(evG1, s2);
    // layer-2 weights (overlap agg1)
    k_convW<<<(96 * 384 + TB - 1) / TB, TB, 0, s2>>>(Wm2, 96, 384, 0);
    k_convAtt<<<1, 512, 0, s2>>>(Wm2, att2, bm2, 96, 96, 384);
    cudaEventRecord(evC2, s2);

    // ---- agg1 h0 (s0): needs CSR (order) + GEMM1; writes h1 + h1H ----
    cudaStreamWaitEvent(s0, evG1, 0);
    k_agg<96><<<aggH0, TB, 0, s0>>>(M8A, aNA, S, h1, h1H, 0, NS);
    cudaEventRecord(evA1h0, s0);
    k_agg<96><<<aggH1, TB, 0, s0>>>(M8A, aNA, S, h1, h1H, NS, NN);
    cudaEventRecord(evA1h1, s0);

    // ---- gemm2 h0 on s2 (384 cols, no aN); then alphaGemv2 (full h1 -> aNB) ----
    cudaStreamWaitEvent(s2, evA1h0, 0);
    k_hgemm<96><<<dim3(rbH0, 3), TB, 0, s2>>>(h1H, bm2, bm2, M8B, S, aNB, 0, NN, 384, 384, 384, 384, 96);
    cudaStreamWaitEvent(s2, evA1h1, 0);
    k_alphaGemv<<<warpNodeBlocks, TB, 0, s2>>>(h1, aNB, 384);
    cudaEventRecord(evG2h0, s2);

    // ---- gemm2 h1 on s0 (after agg1 h1 in order; needs conv2) ----
    cudaStreamWaitEvent(s0, evC2, 0);
    k_hgemm<96><<<dim3(rbH1, 3), TB, 0, s0>>>(h1H, bm2, bm2, M8B, S, aNB, NS, NN, 384, 384, 384, 384, 96);
    cudaEventRecord(evG2h1, s0);

    // ---- layer-3 weights on s2: need gemm2 fully done reading d_Wh ----
    cudaStreamWaitEvent(s2, evG2h1, 0);
    k_convW<<<(96 * 256 + TB - 1) / TB, TB, 0, s2>>>(Wm3, 96, 256, 0);
    k_convW<<<(96 * 64 + TB - 1) / TB, TB, 0, s2>>>(Ws3, 96, 64, 256);
    k_convAtt<<<1, 512, 0, s2>>>(Wm3, att3, bm3, 96, 64, 320);
    cudaEventRecord(evC3, s2);

    // ---- agg2 h0 (s0): needs gemm2 h0 + alphaGemv2 (evG2h0) + gemm2 h1 (order) ----
    cudaStreamWaitEvent(s0, evG2h0, 0);
    k_agg<96><<<aggH0, TB, 0, s0>>>(M8B, aNB, h1, h2, h2H, 0, NS);
    cudaEventRecord(evA2h0, s0);
    k_agg<96><<<aggH1, TB, 0, s0>>>(M8B, aNB, h1, h2, h2H, NS, NN);

    // ---- gemm3 h0 on s2: needs agg2 h0 + conv3 (s2 order); writes M8A/aNA/S ----
    cudaStreamWaitEvent(s2, evA2h0, 0);
    k_hgemm<96><<<dim3(rbH0, 3), TB, 0, s2>>>(h2H, bm3, bs3, M8A, S, aNA, 0, NN, 324, 256, 320, 256, 64);
    cudaEventRecord(evG3h0, s2);

    // ---- gemm3 h1 on s0 (after agg2 h1 in order; needs conv3) ----
    cudaStreamWaitEvent(s0, evC3, 0);
    k_hgemm<96><<<dim3(rbH1, 3), TB, 0, s0>>>(h2H, bm3, bs3, M8A, S, aNA, NS, NN, 324, 256, 320, 256, 64);

    // ---- agg3 (s0) ----
    cudaStreamWaitEvent(s0, evG3h0, 0);
    k_agg<64><<<warpNodeBlocks, TB, 0, s0>>>(M8A, aNA, S, h3, ((__half*)0), 0, NN);

    // ---- pool + classifier ----
    cudaStreamWaitEvent(s0, evGst, 0);
    k_pool<<<NG, 256, 0, s0>>>();
    k_fc<<<1, 64, 0, s0>>>(Wfc, bfc, out);
}